// round 12
// baseline (speedup 1.0000x reference)
#include <cuda_runtime.h>
#include <cuda_fp16.h>
#include <math.h>

#define B_    8
#define C_    256
#define HW_   2304
#define HEADS_ 4
#define DH_   32
#define HID_  128
#define QKV_  384
#define NOUT  (B_*C_*HW_)   // 4718592

// Attention tiling: 128 query rows/CTA, 36 key tiles of 64
#define MT 128
#define NT 64
#define NTILES (HW_/NT)

// SMEM half-element offsets (padded strides for conflict-free ldmatrix)
#define QSTR 40     // 32 halfs data + 8 pad  (80B row)
#define VSTR 72     // 64 halfs data + 8 pad  (144B row)
// Double-buffered K/V: buf stride = one K tile + one V tile
#define A_QH 0                        // Q hi: 128 x 40 = 5120
#define A_K0 (A_QH + MT*QSTR)         // 5120
#define A_V0 (A_K0 + NT*QSTR)         // 7680
#define A_BSTR (NT*QSTR + DH_*VSTR)   // 4864 halfs per buffer
#define A_HALFS (A_K0 + 2*A_BSTR)     // 14848 halfs = 29696 B

// tc_gemm SMEM layout (halfs): W-hi, W-lo (128 m x 40), X-hi (128 n x 40)
#define G_WH 0
#define G_WL 5120
#define G_XH 10240
#define G_HALFS 15360                 // 30720 B

typedef unsigned long long ull;

// Scratch (static device globals: allowed; allocs are not)
__device__ float  g_qkv[B_*QKV_*HW_];   // [b, 384, 2304]
__device__ float  g_att[B_*HID_*HW_];   // [b, 128, 2304]
__device__ double g_acc[3];             // [sumsq_qkv, e_attn, sumsq_out]

// ---------------- packed f32x2 helpers (Blackwell FFMA2) -------------------
__device__ __forceinline__ ull pk2(float lo, float hi) {
    ull r; asm("mov.b64 %0, {%1,%2};" : "=l"(r) : "f"(lo), "f"(hi)); return r;
}
__device__ __forceinline__ void upk2(ull v, float& lo, float& hi) {
    asm("mov.b64 {%0,%1}, %2;" : "=f"(lo), "=f"(hi) : "l"(v));
}
__device__ __forceinline__ ull fma2(ull a, ull b, ull c) {
    ull d; asm("fma.rn.f32x2 %0, %1, %2, %3;" : "=l"(d) : "l"(a), "l"(b), "l"(c));
    return d;
}
__device__ __forceinline__ ull add2(ull a, ull b) {
    ull d; asm("add.rn.f32x2 %0, %1, %2;" : "=l"(d) : "l"(a), "l"(b));
    return d;
}
__device__ __forceinline__ ull mul2(ull a, ull b) {
    ull d; asm("mul.rn.f32x2 %0, %1, %2;" : "=l"(d) : "l"(a), "l"(b));
    return d;
}

// ---------------- fp16 pack/unpack + MUFU exp2 -----------------------------
__device__ __forceinline__ unsigned f2h2(float lo, float hi) {
    unsigned u;  // PTX cvt: first source -> HIGH half
    asm("cvt.rn.f16x2.f32 %0, %1, %2;" : "=r"(u) : "f"(hi), "f"(lo));
    return u;
}
__device__ __forceinline__ void h2tof(unsigned u, float& lo, float& hi) {
    asm("{.reg .b16 l, h;\n\t mov.b32 {l, h}, %2;\n\t"
        "cvt.f32.f16 %0, l;\n\t cvt.f32.f16 %1, h;}"
        : "=f"(lo), "=f"(hi) : "r"(u));
}
__device__ __forceinline__ unsigned ex2h2(unsigned y) {
    unsigned p; asm("ex2.approx.f16x2 %0, %1;" : "=r"(p) : "r"(y));
    return p;
}

// ---------------- mma.sync + ldmatrix (sm_80 path; no 'a'-gated features) --
__device__ __forceinline__ void mma16816(float* c,
    unsigned a0, unsigned a1, unsigned a2, unsigned a3,
    unsigned b0, unsigned b1)
{
    asm volatile(
        "mma.sync.aligned.m16n8k16.row.col.f32.f16.f16.f32 "
        "{%0,%1,%2,%3}, {%4,%5,%6,%7}, {%8,%9}, {%0,%1,%2,%3};"
        : "+f"(c[0]), "+f"(c[1]), "+f"(c[2]), "+f"(c[3])
        : "r"(a0), "r"(a1), "r"(a2), "r"(a3), "r"(b0), "r"(b1));
}
__device__ __forceinline__ void ldsm4(unsigned* r, unsigned addr) {
    asm volatile("ldmatrix.sync.aligned.m8n8.x4.shared.b16 {%0,%1,%2,%3}, [%4];"
        : "=r"(r[0]), "=r"(r[1]), "=r"(r[2]), "=r"(r[3]) : "r"(addr));
}

// Block-reduce a float and atomically add (as double) into g_acc[idx].
__device__ __forceinline__ void block_accum(float v, int idx, float* red) {
    #pragma unroll
    for (int off = 16; off > 0; off >>= 1)
        v += __shfl_down_sync(0xFFFFFFFFu, v, off);
    int lane = threadIdx.x & 31, warp = threadIdx.x >> 5;
    if (lane == 0) red[warp] = v;
    __syncthreads();
    if (warp == 0) {
        int nw = (blockDim.x + 31) >> 5;
        float s = (lane < nw) ? red[lane] : 0.0f;
        #pragma unroll
        for (int off = 4; off > 0; off >>= 1)
            s += __shfl_down_sync(0xFFFFFFFFu, s, off);
        if (lane == 0) atomicAdd(&g_acc[idx], (double)s);
    }
}

// ---------------------------------------------------------------------------
// Tensor-core channel GEMM: C[b,m,n] = sum_k Wt[m,k]*X[b,k,n] + bias[m]
// 2-pass fp16 split on W: C = (Wh+Wl)*Xh. Unchanged (passing since R9).
// ---------------------------------------------------------------------------
__global__ void __launch_bounds__(256, 2)
tc_gemm_kernel(const float* __restrict__ Wt, const float* __restrict__ X,
               const float* __restrict__ bias, float* __restrict__ Cdst,
               int M, int K, int accIdx)
{
    __shared__ __align__(16) __half smh[G_HALFS];
    __shared__ float red[8];

    const int tid  = threadIdx.x;
    const int lane = tid & 31;
    const int w    = tid >> 5;
    const int lr   = lane & 7;
    const int sel  = lane >> 3;
    const int g    = lane >> 2;
    const int qt   = lane & 3;

    const int bz = blockIdx.z;
    const int m0 = blockIdx.y * 128;
    const int n0 = blockIdx.x * 128;
    const float* Xb = X + (size_t)bz * K * HW_;

    const unsigned sbase = (unsigned)__cvta_generic_to_shared(smh);

    float C[16][4] = {};

    const int krow  = lr + 8 * (sel >> 1);
    const int kcolp = 8 * (sel & 1);
    const int arow  = 16 * w + lr + 8 * (sel & 1);
    const int acolp = 8 * (sel >> 1);

    for (int k0 = 0; k0 < K; k0 += 32) {
        __syncthreads();
        // ---- W chunk: 128 m x 32 k, split hi/lo ----
        {
            const int m = tid >> 1;
            const int khw = (tid & 1) * 16;
            const float4* wrow = (const float4*)(Wt + (size_t)(m0 + m) * K + k0 + khw);
            #pragma unroll
            for (int r4 = 0; r4 < 4; r4++) {
                float4 wv = wrow[r4];
                unsigned hp0 = f2h2(wv.x, wv.y);
                unsigned hp1 = f2h2(wv.z, wv.w);
                float rx, ry, rz, rw;
                h2tof(hp0, rx, ry);
                h2tof(hp1, rz, rw);
                unsigned lp0 = f2h2(wv.x - rx, wv.y - ry);
                unsigned lp1 = f2h2(wv.z - rz, wv.w - rw);
                int base = m * QSTR + khw + 4 * r4;
                *(unsigned*)&smh[G_WH + base]     = hp0;
                *(unsigned*)&smh[G_WH + base + 2] = hp1;
                *(unsigned*)&smh[G_WL + base]     = lp0;
                *(unsigned*)&smh[G_WL + base + 2] = lp1;
            }
        }
        // ---- X chunk: 128 n x 32 k (transposed store), hi only ----
        {
            const int n = tid & 127;
            const int khx = (tid >> 7) * 16;
            #pragma unroll
            for (int r = 0; r < 16; r++) {
                float xf = Xb[(size_t)(k0 + khx + r) * HW_ + n0 + n];
                smh[G_XH + n * QSTR + khx + r] = __float2half_rn(xf);
            }
        }
        __syncthreads();

        // ---- A frags (hi+lo), then MMA over 16 n-blocks ----
        #pragma unroll
        for (int s = 0; s < 2; s++) {
            unsigned ah[4], al[4];
            ldsm4(ah, sbase + (G_WH + arow * QSTR + 16 * s + acolp) * 2);
            ldsm4(al, sbase + (G_WL + arow * QSTR + 16 * s + acolp) * 2);
            #pragma unroll
            for (int nbp = 0; nbp < 8; nbp++) {
                unsigned bv[4];
                int off = G_XH + (16 * nbp + krow) * QSTR + 16 * s + kcolp;
                ldsm4(bv, sbase + off * 2);
                mma16816(C[2 * nbp],     ah[0], ah[1], ah[2], ah[3], bv[0], bv[1]);
                mma16816(C[2 * nbp + 1], ah[0], ah[1], ah[2], ah[3], bv[2], bv[3]);
                mma16816(C[2 * nbp],     al[0], al[1], al[2], al[3], bv[0], bv[1]);
                mma16816(C[2 * nbp + 1], al[0], al[1], al[2], al[3], bv[2], bv[3]);
            }
        }
    }

    // ---- epilogue: bias, store, sumsq ----
    const int row0 = m0 + 16 * w + g;
    const int row1 = row0 + 8;
    const float b0 = bias[row0];
    const float b1 = bias[row1];
    float* c0 = Cdst + ((size_t)bz * M + row0) * HW_ + n0;
    float* c1 = Cdst + ((size_t)bz * M + row1) * HW_ + n0;
    float ss = 0.0f;
    #pragma unroll
    for (int nb = 0; nb < 16; nb++) {
        int n = 8 * nb + 2 * qt;
        float v0 = C[nb][0] + b0;
        float v1 = C[nb][1] + b0;
        float v2 = C[nb][2] + b1;
        float v3 = C[nb][3] + b1;
        c0[n] = v0; c0[n + 1] = v1;
        c1[n] = v2; c1[n + 1] = v3;
        ss = fmaf(v0, v0, ss); ss = fmaf(v1, v1, ss);
        ss = fmaf(v2, v2, ss); ss = fmaf(v3, v3, ss);
    }
    __syncthreads();
    block_accum(ss, accIdx, red);
}

// ---------------------------------------------------------------------------
// Tensor-core flash attention, single-pass fp16, double-buffered, with
// MUFU softmax: p = ex2.approx.f16x2(s*scale*log2e). The f16x2 result IS
// the PV A-frag; l,t accumulate from the same fp16 p (exactly-consistent
// normalization). t kept in log2 domain, *ln2 at finalize.
// K staged via STS.128 (j-row-major), V staged via 2xLDG.128 + STS.128
// (d-row-major) with per-destination thread mappings.
// Grid: (HW_/128, B_*HEADS_). e_attn -> g_acc[1].
// ---------------------------------------------------------------------------
__global__ void __launch_bounds__(256, 2)
attn_kernel()
{
    __shared__ __align__(16) __half smh[A_HALFS];
    __shared__ float red[8];

    const int tid  = threadIdx.x;
    const int lane = tid & 31;
    const int w    = tid >> 5;
    const int lr   = lane & 7;
    const int sel  = lane >> 3;
    const int g    = lane >> 2;
    const int qt   = lane & 3;

    const int bh = blockIdx.y, b = bh >> 2, h = bh & 3;
    const int m0 = blockIdx.x * MT;

    const float* qb = g_qkv + ((size_t)b*QKV_ +            h*DH_) * HW_;
    const float* kb = g_qkv + ((size_t)b*QKV_ + HID_     + h*DH_) * HW_;
    const float* vb = g_qkv + ((size_t)b*QKV_ + 2*HID_   + h*DH_) * HW_;

    const unsigned sbase = (unsigned)__cvta_generic_to_shared(smh);

    // ---- load Q (fp16 hi only, unscaled) ------------------------------
    {
        const int i = tid & 127;
        const int dg = tid >> 7;          // 0 or 1
        #pragma unroll
        for (int r = 0; r < 16; r++) {
            int d = dg * 16 + r;
            smh[A_QH + i * QSTR + d] = __float2half_rn(qb[(size_t)d * HW_ + m0 + i]);
        }
    }

    // K staging mapping: row jk (0..63), 8 consecutive d at kd0
    const int jk  = tid & 63;
    const int kd0 = (tid >> 6) * 8;       // 0,8,16,24
    // V staging mapping: row vd (0..31), 8 consecutive j at vj0
    const int vd  = tid & 31;
    const int vj0 = (tid >> 5) * 8;       // 0..56

    // ---- prologue: tile0 -> smem buf0; tile1 -> regs ------------------
    float kreg[8];
    float4 va0, va1;
    #pragma unroll
    for (int r = 0; r < 8; r++)
        kreg[r] = kb[(size_t)(kd0 + r) * HW_ + jk];
    {
        const float4* vp = (const float4*)(vb + (size_t)vd * HW_ + vj0);
        va0 = vp[0]; va1 = vp[1];
    }
    {
        uint4 kp = make_uint4(f2h2(kreg[0], kreg[1]), f2h2(kreg[2], kreg[3]),
                              f2h2(kreg[4], kreg[5]), f2h2(kreg[6], kreg[7]));
        *(uint4*)&smh[A_K0 + jk * QSTR + kd0] = kp;
        uint4 vp4 = make_uint4(f2h2(va0.x, va0.y), f2h2(va0.z, va0.w),
                               f2h2(va1.x, va1.y), f2h2(va1.z, va1.w));
        *(uint4*)&smh[A_V0 + vd * VSTR + vj0] = vp4;
    }
    #pragma unroll
    for (int r = 0; r < 8; r++)
        kreg[r] = kb[(size_t)(kd0 + r) * HW_ + NT + jk];
    {
        const float4* vp = (const float4*)(vb + (size_t)vd * HW_ + NT + vj0);
        va0 = vp[0]; va1 = vp[1];
    }
    __syncthreads();

    // ---- resident Q A-frags: aq[kchunk][4] ----------------------------
    unsigned aq[2][4];
    {
        int qrow = 16 * w + lr + 8 * (sel & 1);
        #pragma unroll
        for (int c = 0; c < 2; c++)
            ldsm4(aq[c], sbase + (A_QH + qrow * QSTR + 16 * c + 8 * (sel >> 1)) * 2);
    }

    // scale * log2(e): softmax in log2 domain, |y| <= ~0.4
    const float SCL = 0.17677669529663687f * 1.4426950408889634f;

    float O[4][4] = {};                 // 16 rows x 32 d, fp32, lives all tiles
    ull l2g = 0, t2g = 0, l2h = 0, t2h = 0;

    const int krow = lr + 8 * (sel >> 1);
    const int kcolp = 8 * (sel & 1);

    for (int tile = 0; tile < NTILES; tile++) {
        const unsigned cbuf = (tile & 1) ? A_BSTR : 0u;   // read buffer offset
        const unsigned nbuf = (tile & 1) ? 0u : A_BSTR;   // write buffer offset

        // ---- commit prefetched tile t+1 into the other buffer ---------
        if (tile + 1 < NTILES) {
            uint4 kp = make_uint4(f2h2(kreg[0], kreg[1]), f2h2(kreg[2], kreg[3]),
                                  f2h2(kreg[4], kreg[5]), f2h2(kreg[6], kreg[7]));
            *(uint4*)&smh[A_K0 + nbuf + jk * QSTR + kd0] = kp;
            uint4 vp4 = make_uint4(f2h2(va0.x, va0.y), f2h2(va0.z, va0.w),
                                   f2h2(va1.x, va1.y), f2h2(va1.z, va1.w));
            *(uint4*)&smh[A_V0 + nbuf + vd * VSTR + vj0] = vp4;
        }
        // ---- prefetch tile t+2 (LDGs overlap the MMAs below) ----------
        if (tile + 2 < NTILES) {
            const int jn = (tile + 2) * NT;
            #pragma unroll
            for (int r = 0; r < 8; r++)
                kreg[r] = kb[(size_t)(kd0 + r) * HW_ + jn + jk];
            const float4* vp = (const float4*)(vb + (size_t)vd * HW_ + jn + vj0);
            va0 = vp[0]; va1 = vp[1];
        }

        // ---- S = qh*kh (single pass, from current buffer) -------------
        float sC[8][4] = {};
        #pragma unroll
        for (int cc = 0; cc < 2; cc++) {
            #pragma unroll
            for (int ntp = 0; ntp < 4; ntp++) {
                unsigned bv[4];
                unsigned off = A_K0 + cbuf + (16 * ntp + krow) * QSTR + 16 * cc + kcolp;
                ldsm4(bv, sbase + off * 2);
                mma16816(sC[2 * ntp],     aq[cc][0], aq[cc][1], aq[cc][2], aq[cc][3], bv[0], bv[1]);
                mma16816(sC[2 * ntp + 1], aq[cc][0], aq[cc][1], aq[cc][2], aq[cc][3], bv[2], bv[3]);
            }
        }

        // ---- softmax: p = ex2(y), y = s*SCL (log2 domain), via MUFU ---
        unsigned PH[8][2];
        #pragma unroll
        for (int nt = 0; nt < 8; nt++) {
            // rows g
            float y0 = sC[nt][0] * SCL;
            float y1 = sC[nt][1] * SCL;
            unsigned ph = ex2h2(f2h2(y0, y1));
            PH[nt][0] = ph;
            float p0, p1; h2tof(ph, p0, p1);
            ull p2 = pk2(p0, p1);
            t2g = fma2(p2, pk2(y0, y1), t2g);
            l2g = add2(l2g, p2);
            // rows g+8
            y0 = sC[nt][2] * SCL;
            y1 = sC[nt][3] * SCL;
            ph = ex2h2(f2h2(y0, y1));
            PH[nt][1] = ph;
            h2tof(ph, p0, p1);
            p2 = pk2(p0, p1);
            t2h = fma2(p2, pk2(y0, y1), t2h);
            l2h = add2(l2h, p2);
        }

        // ---- O += ph*vh (single pass, from current buffer) ------------
        #pragma unroll
        for (int kc = 0; kc < 4; kc++) {
            unsigned a0 = PH[2 * kc][0],     a1 = PH[2 * kc][1];
            unsigned a2 = PH[2 * kc + 1][0], a3 = PH[2 * kc + 1][1];
            #pragma unroll
            for (int ndp = 0; ndp < 2; ndp++) {
                unsigned bv[4];
                unsigned off = A_V0 + cbuf + (16 * ndp + krow) * VSTR + 16 * kc + kcolp;
                ldsm4(bv, sbase + off * 2);
                mma16816(O[2 * ndp],     a0, a1, a2, a3, bv[0], bv[1]);
                mma16816(O[2 * ndp + 1], a0, a1, a2, a3, bv[2], bv[3]);
            }
        }

        __syncthreads();   // single barrier: buf[cur] reads + buf[next] writes done
    }

    // ---- finalize: row sums over quad lanes, normalize, write ---------
    const float LN2 = 0.6931471805599453f;
    float lg, tg, lh, th, tmp;
    upk2(l2g, lg, tmp); lg += tmp;
    upk2(t2g, tg, tmp); tg += tmp;
    upk2(l2h, lh, tmp); lh += tmp;
    upk2(t2h, th, tmp); th += tmp;
    #pragma unroll
    for (int off = 1; off <= 2; off <<= 1) {
        lg += __shfl_xor_sync(0xFFFFFFFFu, lg, off);
        tg += __shfl_xor_sync(0xFFFFFFFFu, tg, off);
        lh += __shfl_xor_sync(0xFFFFFFFFu, lh, off);
        th += __shfl_xor_sync(0xFFFFFFFFu, th, off);
    }
    float inv0 = 1.0f / lg;
    float inv1 = 1.0f / lh;

    float* obase = g_att + ((size_t)b * HID_ + h * DH_) * HW_;
    const int row0 = m0 + 16 * w + g;
    const int row1 = row0 + 8;
    #pragma unroll
    for (int ntd = 0; ntd < 4; ntd++) {
        int d = 8 * ntd + 2 * qt;
        obase[(size_t)d * HW_ + row0]       = O[ntd][0] * inv0;
        obase[(size_t)(d + 1) * HW_ + row0] = O[ntd][1] * inv0;
        obase[(size_t)d * HW_ + row1]       = O[ntd][2] * inv1;
        obase[(size_t)(d + 1) * HW_ + row1] = O[ntd][3] * inv1;
    }

    float ev = 0.0f;
    if (qt == 0)
        ev = (tg * LN2 * inv0 - logf(lg)) + (th * LN2 * inv1 - logf(lh));
    __syncthreads();
    block_accum(ev, 1, red);
}

__global__ void zero_acc_kernel() {
    if (threadIdx.x < 3) g_acc[threadIdx.x] = 0.0;
}

// Empty marker so the ncu capture slot lands on attn_kernel.
__global__ void marker_kernel() {}

__global__ void energy_kernel(float* __restrict__ out, int out_size) {
    if (out_size > NOUT) {
        double e = -0.5 * g_acc[0] + g_acc[1] - 0.5 * g_acc[2];
        out[NOUT] = (float)e;
    }
}

extern "C" void kernel_launch(void* const* d_in, const int* in_sizes, int n_in,
                              void* d_out, int out_size)
{
    const float* x     = (const float*)d_in[0];
    const float* w_qkv = (const float*)d_in[1];
    const float* b_qkv = (const float*)d_in[2];
    const float* w_out = (const float*)d_in[3];
    const float* b_out = (const float*)d_in[4];
    float* out = (float*)d_out;

    void *pqkv = nullptr, *patt = nullptr;
    cudaGetSymbolAddress(&pqkv, g_qkv);
    cudaGetSymbolAddress(&patt, g_att);

    zero_acc_kernel<<<1, 32>>>();
    tc_gemm_kernel<<<dim3(HW_ / 128, QKV_ / 128, B_), 256>>>(
        w_qkv, x, b_qkv, (float*)pqkv, QKV_, C_, 0);
    marker_kernel<<<1, 32>>>();
    attn_kernel<<<dim3(HW_ / MT, B_ * HEADS_), 256>>>();
    tc_gemm_kernel<<<dim3(HW_ / 128, C_ / 128, B_), 256>>>(
        w_out, (const float*)patt, b_out, out, C_, HID_, 2);
    energy_kernel<<<1, 1>>>(out, out_size);
}

// round 13
// speedup vs baseline: 1.5066x; 1.5066x over previous
#include <cuda_runtime.h>
#include <cuda_fp16.h>
#include <math.h>

#define B_    8
#define C_    256
#define HW_   2304
#define HEADS_ 4
#define DH_   32
#define HID_  128
#define QKV_  384
#define NOUT  (B_*C_*HW_)   // 4718592

// Attention tiling: 128 query rows/CTA, 36 key tiles of 64
#define MT 128
#define NT 64
#define NTILES (HW_/NT)

// SMEM half-element offsets (padded strides for conflict-free ldmatrix)
#define QSTR 40     // 32 halfs data + 8 pad  (80B row)
#define VSTR 72     // 64 halfs data + 8 pad  (144B row)
// Double-buffered K/V: buf stride = one K tile + one V tile
#define A_QH 0                        // Q hi: 128 x 40 = 5120
#define A_K0 (A_QH + MT*QSTR)         // 5120
#define A_V0 (A_K0 + NT*QSTR)         // 7680
#define A_BSTR (NT*QSTR + DH_*VSTR)   // 4864 halfs per buffer
#define A_HALFS (A_K0 + 2*A_BSTR)     // 14848 halfs = 29696 B

// tc_gemm SMEM layout (halfs): W-hi, W-lo (128 m x 40), X-hi (128 n x 40)
#define G_WH 0
#define G_WL 5120
#define G_XH 10240
#define G_HALFS 15360                 // 30720 B

typedef unsigned long long ull;

// Scratch (static device globals: allowed; allocs are not)
__device__ float  g_qkv[B_*QKV_*HW_];   // [b, 384, 2304]
__device__ float  g_att[B_*HID_*HW_];   // [b, 128, 2304]
__device__ double g_acc[3];             // [sumsq_qkv, e_attn, sumsq_out]

// ---------------- packed f32x2 helpers (Blackwell FFMA2) -------------------
__device__ __forceinline__ ull pk2(float lo, float hi) {
    ull r; asm("mov.b64 %0, {%1,%2};" : "=l"(r) : "f"(lo), "f"(hi)); return r;
}
__device__ __forceinline__ void upk2(ull v, float& lo, float& hi) {
    asm("mov.b64 {%0,%1}, %2;" : "=f"(lo), "=f"(hi) : "l"(v));
}
__device__ __forceinline__ ull fma2(ull a, ull b, ull c) {
    ull d; asm("fma.rn.f32x2 %0, %1, %2, %3;" : "=l"(d) : "l"(a), "l"(b), "l"(c));
    return d;
}
__device__ __forceinline__ ull add2(ull a, ull b) {
    ull d; asm("add.rn.f32x2 %0, %1, %2;" : "=l"(d) : "l"(a), "l"(b));
    return d;
}
__device__ __forceinline__ ull mul2(ull a, ull b) {
    ull d; asm("mul.rn.f32x2 %0, %1, %2;" : "=l"(d) : "l"(a), "l"(b));
    return d;
}

// ---------------- fp16 pack/unpack + MUFU exp2 -----------------------------
__device__ __forceinline__ unsigned f2h2(float lo, float hi) {
    unsigned u;  // PTX cvt: first source -> HIGH half
    asm("cvt.rn.f16x2.f32 %0, %1, %2;" : "=r"(u) : "f"(hi), "f"(lo));
    return u;
}
__device__ __forceinline__ void h2tof(unsigned u, float& lo, float& hi) {
    asm("{.reg .b16 l, h;\n\t mov.b32 {l, h}, %2;\n\t"
        "cvt.f32.f16 %0, l;\n\t cvt.f32.f16 %1, h;}"
        : "=f"(lo), "=f"(hi) : "r"(u));
}
__device__ __forceinline__ unsigned ex2h2(unsigned y) {
    unsigned p; asm("ex2.approx.f16x2 %0, %1;" : "=r"(p) : "r"(y));
    return p;
}

// ---------------- mma.sync + ldmatrix (sm_80 path; no 'a'-gated features) --
__device__ __forceinline__ void mma16816(float* c,
    unsigned a0, unsigned a1, unsigned a2, unsigned a3,
    unsigned b0, unsigned b1)
{
    asm volatile(
        "mma.sync.aligned.m16n8k16.row.col.f32.f16.f16.f32 "
        "{%0,%1,%2,%3}, {%4,%5,%6,%7}, {%8,%9}, {%0,%1,%2,%3};"
        : "+f"(c[0]), "+f"(c[1]), "+f"(c[2]), "+f"(c[3])
        : "r"(a0), "r"(a1), "r"(a2), "r"(a3), "r"(b0), "r"(b1));
}
__device__ __forceinline__ void ldsm4(unsigned* r, unsigned addr) {
    asm volatile("ldmatrix.sync.aligned.m8n8.x4.shared.b16 {%0,%1,%2,%3}, [%4];"
        : "=r"(r[0]), "=r"(r[1]), "=r"(r[2]), "=r"(r[3]) : "r"(addr));
}

// Block-reduce a float and atomically add (as double) into g_acc[idx].
__device__ __forceinline__ void block_accum(float v, int idx, float* red) {
    #pragma unroll
    for (int off = 16; off > 0; off >>= 1)
        v += __shfl_down_sync(0xFFFFFFFFu, v, off);
    int lane = threadIdx.x & 31, warp = threadIdx.x >> 5;
    if (lane == 0) red[warp] = v;
    __syncthreads();
    if (warp == 0) {
        int nw = (blockDim.x + 31) >> 5;
        float s = (lane < nw) ? red[lane] : 0.0f;
        #pragma unroll
        for (int off = 4; off > 0; off >>= 1)
            s += __shfl_down_sync(0xFFFFFFFFu, s, off);
        if (lane == 0) atomicAdd(&g_acc[idx], (double)s);
    }
}

// ---------------------------------------------------------------------------
// Tensor-core channel GEMM: C[b,m,n] = sum_k Wt[m,k]*X[b,k,n] + bias[m]
// 2-pass fp16 split on W: C = (Wh+Wl)*Xh. Unchanged (passing since R9).
// ---------------------------------------------------------------------------
__global__ void __launch_bounds__(256, 2)
tc_gemm_kernel(const float* __restrict__ Wt, const float* __restrict__ X,
               const float* __restrict__ bias, float* __restrict__ Cdst,
               int M, int K, int accIdx)
{
    __shared__ __align__(16) __half smh[G_HALFS];
    __shared__ float red[8];

    const int tid  = threadIdx.x;
    const int lane = tid & 31;
    const int w    = tid >> 5;
    const int lr   = lane & 7;
    const int sel  = lane >> 3;
    const int g    = lane >> 2;
    const int qt   = lane & 3;

    const int bz = blockIdx.z;
    const int m0 = blockIdx.y * 128;
    const int n0 = blockIdx.x * 128;
    const float* Xb = X + (size_t)bz * K * HW_;

    const unsigned sbase = (unsigned)__cvta_generic_to_shared(smh);

    float C[16][4] = {};

    const int krow  = lr + 8 * (sel >> 1);
    const int kcolp = 8 * (sel & 1);
    const int arow  = 16 * w + lr + 8 * (sel & 1);
    const int acolp = 8 * (sel >> 1);

    for (int k0 = 0; k0 < K; k0 += 32) {
        __syncthreads();
        // ---- W chunk: 128 m x 32 k, split hi/lo ----
        {
            const int m = tid >> 1;
            const int khw = (tid & 1) * 16;
            const float4* wrow = (const float4*)(Wt + (size_t)(m0 + m) * K + k0 + khw);
            #pragma unroll
            for (int r4 = 0; r4 < 4; r4++) {
                float4 wv = wrow[r4];
                unsigned hp0 = f2h2(wv.x, wv.y);
                unsigned hp1 = f2h2(wv.z, wv.w);
                float rx, ry, rz, rw;
                h2tof(hp0, rx, ry);
                h2tof(hp1, rz, rw);
                unsigned lp0 = f2h2(wv.x - rx, wv.y - ry);
                unsigned lp1 = f2h2(wv.z - rz, wv.w - rw);
                int base = m * QSTR + khw + 4 * r4;
                *(unsigned*)&smh[G_WH + base]     = hp0;
                *(unsigned*)&smh[G_WH + base + 2] = hp1;
                *(unsigned*)&smh[G_WL + base]     = lp0;
                *(unsigned*)&smh[G_WL + base + 2] = lp1;
            }
        }
        // ---- X chunk: 128 n x 32 k (transposed store), hi only ----
        {
            const int n = tid & 127;
            const int khx = (tid >> 7) * 16;
            #pragma unroll
            for (int r = 0; r < 16; r++) {
                float xf = Xb[(size_t)(k0 + khx + r) * HW_ + n0 + n];
                smh[G_XH + n * QSTR + khx + r] = __float2half_rn(xf);
            }
        }
        __syncthreads();

        // ---- A frags (hi+lo), then MMA over 16 n-blocks ----
        #pragma unroll
        for (int s = 0; s < 2; s++) {
            unsigned ah[4], al[4];
            ldsm4(ah, sbase + (G_WH + arow * QSTR + 16 * s + acolp) * 2);
            ldsm4(al, sbase + (G_WL + arow * QSTR + 16 * s + acolp) * 2);
            #pragma unroll
            for (int nbp = 0; nbp < 8; nbp++) {
                unsigned bv[4];
                int off = G_XH + (16 * nbp + krow) * QSTR + 16 * s + kcolp;
                ldsm4(bv, sbase + off * 2);
                mma16816(C[2 * nbp],     ah[0], ah[1], ah[2], ah[3], bv[0], bv[1]);
                mma16816(C[2 * nbp + 1], ah[0], ah[1], ah[2], ah[3], bv[2], bv[3]);
                mma16816(C[2 * nbp],     al[0], al[1], al[2], al[3], bv[0], bv[1]);
                mma16816(C[2 * nbp + 1], al[0], al[1], al[2], al[3], bv[2], bv[3]);
            }
        }
    }

    // ---- epilogue: bias, store, sumsq ----
    const int row0 = m0 + 16 * w + g;
    const int row1 = row0 + 8;
    const float b0 = bias[row0];
    const float b1 = bias[row1];
    float* c0 = Cdst + ((size_t)bz * M + row0) * HW_ + n0;
    float* c1 = Cdst + ((size_t)bz * M + row1) * HW_ + n0;
    float ss = 0.0f;
    #pragma unroll
    for (int nb = 0; nb < 16; nb++) {
        int n = 8 * nb + 2 * qt;
        float v0 = C[nb][0] + b0;
        float v1 = C[nb][1] + b0;
        float v2 = C[nb][2] + b1;
        float v3 = C[nb][3] + b1;
        c0[n] = v0; c0[n + 1] = v1;
        c1[n] = v2; c1[n + 1] = v3;
        ss = fmaf(v0, v0, ss); ss = fmaf(v1, v1, ss);
        ss = fmaf(v2, v2, ss); ss = fmaf(v3, v3, ss);
    }
    __syncthreads();
    block_accum(ss, accIdx, red);
}

// ---------------------------------------------------------------------------
// Tensor-core flash attention: single-pass fp16, double-buffered (R11
// staging: coalesced scalar LDG, lanes cover consecutive j), MUFU softmax
// (R12): p = ex2.approx.f16x2(s*scale*log2e); the f16x2 result IS the PV
// A-frag; l,t accumulate from the same fp16 p; t in log2 domain.
// Grid: (HW_/128, B_*HEADS_). e_attn -> g_acc[1].
// ---------------------------------------------------------------------------
__global__ void __launch_bounds__(256, 2)
attn_kernel()
{
    __shared__ __align__(16) __half smh[A_HALFS];
    __shared__ float red[8];

    const int tid  = threadIdx.x;
    const int lane = tid & 31;
    const int w    = tid >> 5;
    const int lr   = lane & 7;
    const int sel  = lane >> 3;
    const int g    = lane >> 2;
    const int qt   = lane & 3;

    const int bh = blockIdx.y, b = bh >> 2, h = bh & 3;
    const int m0 = blockIdx.x * MT;

    const float* qb = g_qkv + ((size_t)b*QKV_ +            h*DH_) * HW_;
    const float* kb = g_qkv + ((size_t)b*QKV_ + HID_     + h*DH_) * HW_;
    const float* vb = g_qkv + ((size_t)b*QKV_ + 2*HID_   + h*DH_) * HW_;

    const unsigned sbase = (unsigned)__cvta_generic_to_shared(smh);

    // ---- load Q (fp16 hi only, unscaled) ------------------------------
    {
        const int i = tid & 127;
        const int dg = tid >> 7;          // 0 or 1
        #pragma unroll
        for (int r = 0; r < 16; r++) {
            int d = dg * 16 + r;
            smh[A_QH + i * QSTR + d] = __float2half_rn(qb[(size_t)d * HW_ + m0 + i]);
        }
    }

    const int jld = tid & 63;           // K/V load mapping (coalesced in j)
    const int dgl = tid >> 6;           // 0..3

    // ---- prologue: tile0 -> regs -> buf0; tile1 -> regs ---------------
    float kreg[8], vreg[8];
    #pragma unroll
    for (int r = 0; r < 8; r++) {
        int d = dgl * 8 + r;
        kreg[r] = kb[(size_t)d * HW_ + jld];
        vreg[r] = vb[(size_t)d * HW_ + jld];
    }
    #pragma unroll
    for (int r = 0; r < 8; r++) {
        int d = dgl * 8 + r;
        smh[A_K0 + jld * QSTR + d] = __float2half_rn(kreg[r]);
        smh[A_V0 + d * VSTR + jld] = __float2half_rn(vreg[r]);
    }
    #pragma unroll
    for (int r = 0; r < 8; r++) {
        int d = dgl * 8 + r;
        kreg[r] = kb[(size_t)d * HW_ + NT + jld];
        vreg[r] = vb[(size_t)d * HW_ + NT + jld];
    }
    __syncthreads();

    // ---- resident Q A-frags: aq[kchunk][4] ----------------------------
    unsigned aq[2][4];
    {
        int qrow = 16 * w + lr + 8 * (sel & 1);
        #pragma unroll
        for (int c = 0; c < 2; c++)
            ldsm4(aq[c], sbase + (A_QH + qrow * QSTR + 16 * c + 8 * (sel >> 1)) * 2);
    }

    // scale * log2(e): softmax in log2 domain, |y| <= ~0.4
    const float SCL = 0.17677669529663687f * 1.4426950408889634f;

    float O[4][4] = {};                 // 16 rows x 32 d, fp32, lives all tiles
    ull l2g = 0, t2g = 0, l2h = 0, t2h = 0;

    const int krow = lr + 8 * (sel >> 1);
    const int kcolp = 8 * (sel & 1);

    for (int tile = 0; tile < NTILES; tile++) {
        const unsigned cbuf = (tile & 1) ? A_BSTR : 0u;   // read buffer offset
        const unsigned nbuf = (tile & 1) ? 0u : A_BSTR;   // write buffer offset

        // ---- commit prefetched tile t+1 into the other buffer ---------
        if (tile + 1 < NTILES) {
            #pragma unroll
            for (int r = 0; r < 8; r++) {
                int d = dgl * 8 + r;
                smh[A_K0 + nbuf + jld * QSTR + d] = __float2half_rn(kreg[r]);
                smh[A_V0 + nbuf + d * VSTR + jld] = __float2half_rn(vreg[r]);
            }
        }
        // ---- prefetch tile t+2 (LDGs overlap the MMAs below) ----------
        if (tile + 2 < NTILES) {
            const int jn = (tile + 2) * NT + jld;
            #pragma unroll
            for (int r = 0; r < 8; r++) {
                int d = dgl * 8 + r;
                kreg[r] = kb[(size_t)d * HW_ + jn];
                vreg[r] = vb[(size_t)d * HW_ + jn];
            }
        }

        // ---- S = qh*kh (single pass, from current buffer) -------------
        float sC[8][4] = {};
        #pragma unroll
        for (int cc = 0; cc < 2; cc++) {
            #pragma unroll
            for (int ntp = 0; ntp < 4; ntp++) {
                unsigned bv[4];
                unsigned off = A_K0 + cbuf + (16 * ntp + krow) * QSTR + 16 * cc + kcolp;
                ldsm4(bv, sbase + off * 2);
                mma16816(sC[2 * ntp],     aq[cc][0], aq[cc][1], aq[cc][2], aq[cc][3], bv[0], bv[1]);
                mma16816(sC[2 * ntp + 1], aq[cc][0], aq[cc][1], aq[cc][2], aq[cc][3], bv[2], bv[3]);
            }
        }

        // ---- softmax: p = ex2(y), y = s*SCL (log2 domain), via MUFU ---
        unsigned PH[8][2];
        #pragma unroll
        for (int nt = 0; nt < 8; nt++) {
            // rows g
            float y0 = sC[nt][0] * SCL;
            float y1 = sC[nt][1] * SCL;
            unsigned ph = ex2h2(f2h2(y0, y1));
            PH[nt][0] = ph;
            float p0, p1; h2tof(ph, p0, p1);
            ull p2 = pk2(p0, p1);
            t2g = fma2(p2, pk2(y0, y1), t2g);
            l2g = add2(l2g, p2);
            // rows g+8
            y0 = sC[nt][2] * SCL;
            y1 = sC[nt][3] * SCL;
            ph = ex2h2(f2h2(y0, y1));
            PH[nt][1] = ph;
            h2tof(ph, p0, p1);
            p2 = pk2(p0, p1);
            t2h = fma2(p2, pk2(y0, y1), t2h);
            l2h = add2(l2h, p2);
        }

        // ---- O += ph*vh (single pass, from current buffer) ------------
        #pragma unroll
        for (int kc = 0; kc < 4; kc++) {
            unsigned a0 = PH[2 * kc][0],     a1 = PH[2 * kc][1];
            unsigned a2 = PH[2 * kc + 1][0], a3 = PH[2 * kc + 1][1];
            #pragma unroll
            for (int ndp = 0; ndp < 2; ndp++) {
                unsigned bv[4];
                unsigned off = A_V0 + cbuf + (16 * ndp + krow) * VSTR + 16 * kc + kcolp;
                ldsm4(bv, sbase + off * 2);
                mma16816(O[2 * ndp],     a0, a1, a2, a3, bv[0], bv[1]);
                mma16816(O[2 * ndp + 1], a0, a1, a2, a3, bv[2], bv[3]);
            }
        }

        __syncthreads();   // single barrier: buf[cur] reads + buf[next] writes done
    }

    // ---- finalize: row sums over quad lanes, normalize, write ---------
    const float LN2 = 0.6931471805599453f;
    float lg, tg, lh, th, tmp;
    upk2(l2g, lg, tmp); lg += tmp;
    upk2(t2g, tg, tmp); tg += tmp;
    upk2(l2h, lh, tmp); lh += tmp;
    upk2(t2h, th, tmp); th += tmp;
    #pragma unroll
    for (int off = 1; off <= 2; off <<= 1) {
        lg += __shfl_xor_sync(0xFFFFFFFFu, lg, off);
        tg += __shfl_xor_sync(0xFFFFFFFFu, tg, off);
        lh += __shfl_xor_sync(0xFFFFFFFFu, lh, off);
        th += __shfl_xor_sync(0xFFFFFFFFu, th, off);
    }
    float inv0 = 1.0f / lg;
    float inv1 = 1.0f / lh;

    float* obase = g_att + ((size_t)b * HID_ + h * DH_) * HW_;
    const int row0 = m0 + 16 * w + g;
    const int row1 = row0 + 8;
    #pragma unroll
    for (int ntd = 0; ntd < 4; ntd++) {
        int d = 8 * ntd + 2 * qt;
        obase[(size_t)d * HW_ + row0]       = O[ntd][0] * inv0;
        obase[(size_t)(d + 1) * HW_ + row0] = O[ntd][1] * inv0;
        obase[(size_t)d * HW_ + row1]       = O[ntd][2] * inv1;
        obase[(size_t)(d + 1) * HW_ + row1] = O[ntd][3] * inv1;
    }

    float ev = 0.0f;
    if (qt == 0)
        ev = (tg * LN2 * inv0 - logf(lg)) + (th * LN2 * inv1 - logf(lh));
    __syncthreads();
    block_accum(ev, 1, red);
}

__global__ void zero_acc_kernel() {
    if (threadIdx.x < 3) g_acc[threadIdx.x] = 0.0;
}

// Empty marker so the ncu capture slot lands on attn_kernel.
__global__ void marker_kernel() {}

__global__ void energy_kernel(float* __restrict__ out, int out_size) {
    if (out_size > NOUT) {
        double e = -0.5 * g_acc[0] + g_acc[1] - 0.5 * g_acc[2];
        out[NOUT] = (float)e;
    }
}

extern "C" void kernel_launch(void* const* d_in, const int* in_sizes, int n_in,
                              void* d_out, int out_size)
{
    const float* x     = (const float*)d_in[0];
    const float* w_qkv = (const float*)d_in[1];
    const float* b_qkv = (const float*)d_in[2];
    const float* w_out = (const float*)d_in[3];
    const float* b_out = (const float*)d_in[4];
    float* out = (float*)d_out;

    void *pqkv = nullptr, *patt = nullptr;
    cudaGetSymbolAddress(&pqkv, g_qkv);
    cudaGetSymbolAddress(&patt, g_att);

    zero_acc_kernel<<<1, 32>>>();
    tc_gemm_kernel<<<dim3(HW_ / 128, QKV_ / 128, B_), 256>>>(
        w_qkv, x, b_qkv, (float*)pqkv, QKV_, C_, 0);
    marker_kernel<<<1, 32>>>();
    attn_kernel<<<dim3(HW_ / MT, B_ * HEADS_), 256>>>();
    tc_gemm_kernel<<<dim3(HW_ / 128, C_ / 128, B_), 256>>>(
        w_out, (const float*)patt, b_out, out, C_, HID_, 2);
    energy_kernel<<<1, 1>>>(out, out_size);
}

// round 15
// speedup vs baseline: 1.5557x; 1.0326x over previous
#include <cuda_runtime.h>
#include <cuda_fp16.h>
#include <math.h>

#define B_    8
#define C_    256
#define HW_   2304
#define HEADS_ 4
#define DH_   32
#define HID_  128
#define QKV_  384
#define NOUT  (B_*C_*HW_)   // 4718592

// Attention tiling: 128 query rows/CTA, 36 key tiles of 64
#define MT 128
#define NT 64
#define NTILES (HW_/NT)

// SMEM half-element offsets (padded strides for conflict-free ldmatrix)
#define QSTR 40     // 32 halfs data + 8 pad  (80B row)
#define VSTR 72     // 64 halfs data + 8 pad  (144B row)
// K and V both stored [d][j] (source orientation), 32 rows x 72 halfs.
// K is consumed via ldmatrix.trans for the S GEMM.
#define A_QH 0                        // Q hi: 128 x 40 = 5120
#define A_K0 (A_QH + MT*QSTR)         // 5120
#define A_V0 (A_K0 + DH_*VSTR)        // 7424
#define A_BSTR (2*DH_*VSTR)           // 4608 halfs per buffer (K+V)
#define A_HALFS (A_K0 + 2*A_BSTR)     // 14336 halfs = 28672 B

// tc_gemm SMEM layout (halfs): W-hi, W-lo (128 m x 40), X-hi (128 n x 40)
#define G_WH 0
#define G_WL 5120
#define G_XH 10240
#define G_HALFS 15360                 // 30720 B

typedef unsigned long long ull;

// Scratch (static device globals: allowed; allocs are not)
__device__ float  g_qkv[B_*QKV_*HW_];   // [b, 384, 2304]
__device__ float  g_att[B_*HID_*HW_];   // [b, 128, 2304]
__device__ double g_acc[3];             // [sumsq_qkv, e_attn, sumsq_out]

// ---------------- packed f32x2 helpers (Blackwell FFMA2) -------------------
__device__ __forceinline__ ull pk2(float lo, float hi) {
    ull r; asm("mov.b64 %0, {%1,%2};" : "=l"(r) : "f"(lo), "f"(hi)); return r;
}
__device__ __forceinline__ void upk2(ull v, float& lo, float& hi) {
    asm("mov.b64 {%0,%1}, %2;" : "=f"(lo), "=f"(hi) : "l"(v));
}
__device__ __forceinline__ ull fma2(ull a, ull b, ull c) {
    ull d; asm("fma.rn.f32x2 %0, %1, %2, %3;" : "=l"(d) : "l"(a), "l"(b), "l"(c));
    return d;
}
__device__ __forceinline__ ull add2(ull a, ull b) {
    ull d; asm("add.rn.f32x2 %0, %1, %2;" : "=l"(d) : "l"(a), "l"(b));
    return d;
}
__device__ __forceinline__ ull mul2(ull a, ull b) {
    ull d; asm("mul.rn.f32x2 %0, %1, %2;" : "=l"(d) : "l"(a), "l"(b));
    return d;
}

// ---------------- fp16 pack/unpack + MUFU exp2 -----------------------------
__device__ __forceinline__ unsigned f2h2(float lo, float hi) {
    unsigned u;  // PTX cvt: first source -> HIGH half
    asm("cvt.rn.f16x2.f32 %0, %1, %2;" : "=r"(u) : "f"(hi), "f"(lo));
    return u;
}
__device__ __forceinline__ void h2tof(unsigned u, float& lo, float& hi) {
    asm("{.reg .b16 l, h;\n\t mov.b32 {l, h}, %2;\n\t"
        "cvt.f32.f16 %0, l;\n\t cvt.f32.f16 %1, h;}"
        : "=f"(lo), "=f"(hi) : "r"(u));
}
__device__ __forceinline__ unsigned ex2h2(unsigned y) {
    unsigned p; asm("ex2.approx.f16x2 %0, %1;" : "=r"(p) : "r"(y));
    return p;
}

// ---------------- mma.sync + ldmatrix (sm_80 path; no 'a'-gated features) --
__device__ __forceinline__ void mma16816(float* c,
    unsigned a0, unsigned a1, unsigned a2, unsigned a3,
    unsigned b0, unsigned b1)
{
    asm volatile(
        "mma.sync.aligned.m16n8k16.row.col.f32.f16.f16.f32 "
        "{%0,%1,%2,%3}, {%4,%5,%6,%7}, {%8,%9}, {%0,%1,%2,%3};"
        : "+f"(c[0]), "+f"(c[1]), "+f"(c[2]), "+f"(c[3])
        : "r"(a0), "r"(a1), "r"(a2), "r"(a3), "r"(b0), "r"(b1));
}
__device__ __forceinline__ void ldsm4(unsigned* r, unsigned addr) {
    asm volatile("ldmatrix.sync.aligned.m8n8.x4.shared.b16 {%0,%1,%2,%3}, [%4];"
        : "=r"(r[0]), "=r"(r[1]), "=r"(r[2]), "=r"(r[3]) : "r"(addr));
}
__device__ __forceinline__ void ldsm4t(unsigned* r, unsigned addr) {
    asm volatile("ldmatrix.sync.aligned.m8n8.x4.trans.shared.b16 {%0,%1,%2,%3}, [%4];"
        : "=r"(r[0]), "=r"(r[1]), "=r"(r[2]), "=r"(r[3]) : "r"(addr));
}

// Block-reduce a float and atomically add (as double) into g_acc[idx].
__device__ __forceinline__ void block_accum(float v, int idx, float* red) {
    #pragma unroll
    for (int off = 16; off > 0; off >>= 1)
        v += __shfl_down_sync(0xFFFFFFFFu, v, off);
    int lane = threadIdx.x & 31, warp = threadIdx.x >> 5;
    if (lane == 0) red[warp] = v;
    __syncthreads();
    if (warp == 0) {
        int nw = (blockDim.x + 31) >> 5;
        float s = (lane < nw) ? red[lane] : 0.0f;
        #pragma unroll
        for (int off = 4; off > 0; off >>= 1)
            s += __shfl_down_sync(0xFFFFFFFFu, s, off);
        if (lane == 0) atomicAdd(&g_acc[idx], (double)s);
    }
}

// ---------------------------------------------------------------------------
// Tensor-core channel GEMM: C[b,m,n] = sum_k Wt[m,k]*X[b,k,n] + bias[m]
// 2-pass fp16 split on W: C = (Wh+Wl)*Xh. Unchanged (passing since R9).
// ---------------------------------------------------------------------------
__global__ void __launch_bounds__(256, 2)
tc_gemm_kernel(const float* __restrict__ Wt, const float* __restrict__ X,
               const float* __restrict__ bias, float* __restrict__ Cdst,
               int M, int K, int accIdx)
{
    __shared__ __align__(16) __half smh[G_HALFS];
    __shared__ float red[8];

    const int tid  = threadIdx.x;
    const int lane = tid & 31;
    const int w    = tid >> 5;
    const int lr   = lane & 7;
    const int sel  = lane >> 3;
    const int g    = lane >> 2;
    const int qt   = lane & 3;

    const int bz = blockIdx.z;
    const int m0 = blockIdx.y * 128;
    const int n0 = blockIdx.x * 128;
    const float* Xb = X + (size_t)bz * K * HW_;

    const unsigned sbase = (unsigned)__cvta_generic_to_shared(smh);

    float C[16][4] = {};

    const int krow  = lr + 8 * (sel >> 1);
    const int kcolp = 8 * (sel & 1);
    const int arow  = 16 * w + lr + 8 * (sel & 1);
    const int acolp = 8 * (sel >> 1);

    for (int k0 = 0; k0 < K; k0 += 32) {
        __syncthreads();
        // ---- W chunk: 128 m x 32 k, split hi/lo ----
        {
            const int m = tid >> 1;
            const int khw = (tid & 1) * 16;
            const float4* wrow = (const float4*)(Wt + (size_t)(m0 + m) * K + k0 + khw);
            #pragma unroll
            for (int r4 = 0; r4 < 4; r4++) {
                float4 wv = wrow[r4];
                unsigned hp0 = f2h2(wv.x, wv.y);
                unsigned hp1 = f2h2(wv.z, wv.w);
                float rx, ry, rz, rw;
                h2tof(hp0, rx, ry);
                h2tof(hp1, rz, rw);
                unsigned lp0 = f2h2(wv.x - rx, wv.y - ry);
                unsigned lp1 = f2h2(wv.z - rz, wv.w - rw);
                int base = m * QSTR + khw + 4 * r4;
                *(unsigned*)&smh[G_WH + base]     = hp0;
                *(unsigned*)&smh[G_WH + base + 2] = hp1;
                *(unsigned*)&smh[G_WL + base]     = lp0;
                *(unsigned*)&smh[G_WL + base + 2] = lp1;
            }
        }
        // ---- X chunk: 128 n x 32 k (transposed store), hi only ----
        {
            const int n = tid & 127;
            const int khx = (tid >> 7) * 16;
            #pragma unroll
            for (int r = 0; r < 16; r++) {
                float xf = Xb[(size_t)(k0 + khx + r) * HW_ + n0 + n];
                smh[G_XH + n * QSTR + khx + r] = __float2half_rn(xf);
            }
        }
        __syncthreads();

        // ---- A frags (hi+lo), then MMA over 16 n-blocks ----
        #pragma unroll
        for (int s = 0; s < 2; s++) {
            unsigned ah[4], al[4];
            ldsm4(ah, sbase + (G_WH + arow * QSTR + 16 * s + acolp) * 2);
            ldsm4(al, sbase + (G_WL + arow * QSTR + 16 * s + acolp) * 2);
            #pragma unroll
            for (int nbp = 0; nbp < 8; nbp++) {
                unsigned bv[4];
                int off = G_XH + (16 * nbp + krow) * QSTR + 16 * s + kcolp;
                ldsm4(bv, sbase + off * 2);
                mma16816(C[2 * nbp],     ah[0], ah[1], ah[2], ah[3], bv[0], bv[1]);
                mma16816(C[2 * nbp + 1], ah[0], ah[1], ah[2], ah[3], bv[2], bv[3]);
                mma16816(C[2 * nbp],     al[0], al[1], al[2], al[3], bv[0], bv[1]);
                mma16816(C[2 * nbp + 1], al[0], al[1], al[2], al[3], bv[2], bv[3]);
            }
        }
    }

    // ---- epilogue: bias, store, sumsq ----
    const int row0 = m0 + 16 * w + g;
    const int row1 = row0 + 8;
    const float b0 = bias[row0];
    const float b1 = bias[row1];
    float* c0 = Cdst + ((size_t)bz * M + row0) * HW_ + n0;
    float* c1 = Cdst + ((size_t)bz * M + row1) * HW_ + n0;
    float ss = 0.0f;
    #pragma unroll
    for (int nb = 0; nb < 16; nb++) {
        int n = 8 * nb + 2 * qt;
        float v0 = C[nb][0] + b0;
        float v1 = C[nb][1] + b0;
        float v2 = C[nb][2] + b1;
        float v3 = C[nb][3] + b1;
        c0[n] = v0; c0[n + 1] = v1;
        c1[n] = v2; c1[n + 1] = v3;
        ss = fmaf(v0, v0, ss); ss = fmaf(v1, v1, ss);
        ss = fmaf(v2, v2, ss); ss = fmaf(v3, v3, ss);
    }
    __syncthreads();
    block_accum(ss, accIdx, red);
}

// ---------------------------------------------------------------------------
// Tensor-core flash attention: single-pass fp16, double-buffered, MUFU
// softmax. K and V both staged in SOURCE orientation [d][j] with fully
// vectorized coalesced LDG.128 + STS.128 (no transpose in staging); the
// S GEMM reads K via ldmatrix.trans (standard K^T b-frag recipe).
// Grid: (HW_/128, B_*HEADS_). e_attn -> g_acc[1].
// ---------------------------------------------------------------------------
__global__ void __launch_bounds__(256, 2)
attn_kernel()
{
    __shared__ __align__(16) __half smh[A_HALFS];
    __shared__ float red[8];

    const int tid  = threadIdx.x;
    const int lane = tid & 31;
    const int w    = tid >> 5;
    const int lr   = lane & 7;
    const int sel  = lane >> 3;
    const int g    = lane >> 2;
    const int qt   = lane & 3;

    const int bh = blockIdx.y, b = bh >> 2, h = bh & 3;
    const int m0 = blockIdx.x * MT;

    const float* qb = g_qkv + ((size_t)b*QKV_ +            h*DH_) * HW_;
    const float* kb = g_qkv + ((size_t)b*QKV_ + HID_     + h*DH_) * HW_;
    const float* vb = g_qkv + ((size_t)b*QKV_ + 2*HID_   + h*DH_) * HW_;

    const unsigned sbase = (unsigned)__cvta_generic_to_shared(smh);

    // ---- load Q (fp16 hi only, unscaled) ------------------------------
    {
        const int i = tid & 127;
        const int dg = tid >> 7;          // 0 or 1
        #pragma unroll
        for (int r = 0; r < 16; r++) {
            int d = dg * 16 + r;
            smh[A_QH + i * QSTR + d] = __float2half_rn(qb[(size_t)d * HW_ + m0 + i]);
        }
    }

    // staging mapping (K and V identical): row d = tid>>3, 8 consecutive j
    const int sd  = tid >> 3;            // 0..31
    const int sj0 = (tid & 7) * 8;       // 0..56

    // ---- prologue: tile0 -> buf0; tile1 -> regs -----------------------
    float4 ka0, ka1, va0, va1;
    {
        const float4* kp = (const float4*)(kb + (size_t)sd * HW_ + sj0);
        ka0 = kp[0]; ka1 = kp[1];
        const float4* vp = (const float4*)(vb + (size_t)sd * HW_ + sj0);
        va0 = vp[0]; va1 = vp[1];
        uint4 kq = make_uint4(f2h2(ka0.x, ka0.y), f2h2(ka0.z, ka0.w),
                              f2h2(ka1.x, ka1.y), f2h2(ka1.z, ka1.w));
        *(uint4*)&smh[A_K0 + sd * VSTR + sj0] = kq;
        uint4 vq = make_uint4(f2h2(va0.x, va0.y), f2h2(va0.z, va0.w),
                              f2h2(va1.x, va1.y), f2h2(va1.z, va1.w));
        *(uint4*)&smh[A_V0 + sd * VSTR + sj0] = vq;
    }
    {
        const float4* kp = (const float4*)(kb + (size_t)sd * HW_ + NT + sj0);
        ka0 = kp[0]; ka1 = kp[1];
        const float4* vp = (const float4*)(vb + (size_t)sd * HW_ + NT + sj0);
        va0 = vp[0]; va1 = vp[1];
    }
    __syncthreads();

    // ---- resident Q A-frags: aq[kchunk][4] ----------------------------
    unsigned aq[2][4];
    {
        int qrow = 16 * w + lr + 8 * (sel & 1);
        #pragma unroll
        for (int c = 0; c < 2; c++)
            ldsm4(aq[c], sbase + (A_QH + qrow * QSTR + 16 * c + 8 * (sel >> 1)) * 2);
    }

    // scale * log2(e): softmax in log2 domain, |y| <= ~0.4
    const float SCL = 0.17677669529663687f * 1.4426950408889634f;

    float O[4][4] = {};                 // 16 rows x 32 d, fp32, lives all tiles
    ull l2g = 0, t2g = 0, l2h = 0, t2h = 0;

    // S b-frag (trans) row/col components: k-row = 16*cc + 8*(sel&1) + lr,
    // n offset = 16*ntp + 8*(sel>>1).
    const int tkrow = 8 * (sel & 1) + lr;
    const int tncol = 8 * (sel >> 1);
    // PV b-frag (non-trans, V rows = d = n): row = lr + 8*(sel>>1), col k = j.
    const int vrow  = lr + 8 * (sel >> 1);
    const int vcolp = 8 * (sel & 1);

    for (int tile = 0; tile < NTILES; tile++) {
        const unsigned cbuf = (tile & 1) ? A_BSTR : 0u;   // read buffer offset
        const unsigned nbuf = (tile & 1) ? 0u : A_BSTR;   // write buffer offset

        // ---- commit prefetched tile t+1 into the other buffer ---------
        if (tile + 1 < NTILES) {
            uint4 kq = make_uint4(f2h2(ka0.x, ka0.y), f2h2(ka0.z, ka0.w),
                                  f2h2(ka1.x, ka1.y), f2h2(ka1.z, ka1.w));
            *(uint4*)&smh[A_K0 + nbuf + sd * VSTR + sj0] = kq;
            uint4 vq = make_uint4(f2h2(va0.x, va0.y), f2h2(va0.z, va0.w),
                                  f2h2(va1.x, va1.y), f2h2(va1.z, va1.w));
            *(uint4*)&smh[A_V0 + nbuf + sd * VSTR + sj0] = vq;
        }
        // ---- prefetch tile t+2 (LDGs overlap the MMAs below) ----------
        if (tile + 2 < NTILES) {
            const int jn = (tile + 2) * NT + sj0;
            const float4* kp = (const float4*)(kb + (size_t)sd * HW_ + jn);
            ka0 = kp[0]; ka1 = kp[1];
            const float4* vp = (const float4*)(vb + (size_t)sd * HW_ + jn);
            va0 = vp[0]; va1 = vp[1];
        }

        // ---- S = qh*kh (K via ldmatrix.trans from [d][j] storage) -----
        float sC[8][4] = {};
        #pragma unroll
        for (int cc = 0; cc < 2; cc++) {
            #pragma unroll
            for (int ntp = 0; ntp < 4; ntp++) {
                unsigned bv[4];
                unsigned off = A_K0 + cbuf + (16 * cc + tkrow) * VSTR + 16 * ntp + tncol;
                ldsm4t(bv, sbase + off * 2);
                mma16816(sC[2 * ntp],     aq[cc][0], aq[cc][1], aq[cc][2], aq[cc][3], bv[0], bv[1]);
                mma16816(sC[2 * ntp + 1], aq[cc][0], aq[cc][1], aq[cc][2], aq[cc][3], bv[2], bv[3]);
            }
        }

        // ---- softmax: p = ex2(y), y = s*SCL (log2 domain), via MUFU ---
        unsigned PH[8][2];
        #pragma unroll
        for (int nt = 0; nt < 8; nt++) {
            // rows g
            float y0 = sC[nt][0] * SCL;
            float y1 = sC[nt][1] * SCL;
            unsigned ph = ex2h2(f2h2(y0, y1));
            PH[nt][0] = ph;
            float p0, p1; h2tof(ph, p0, p1);
            ull p2 = pk2(p0, p1);
            t2g = fma2(p2, pk2(y0, y1), t2g);
            l2g = add2(l2g, p2);
            // rows g+8
            y0 = sC[nt][2] * SCL;
            y1 = sC[nt][3] * SCL;
            ph = ex2h2(f2h2(y0, y1));
            PH[nt][1] = ph;
            h2tof(ph, p0, p1);
            p2 = pk2(p0, p1);
            t2h = fma2(p2, pk2(y0, y1), t2h);
            l2h = add2(l2h, p2);
        }

        // ---- O += ph*vh (V non-trans, rows = d) -----------------------
        #pragma unroll
        for (int kc = 0; kc < 4; kc++) {
            unsigned a0 = PH[2 * kc][0],     a1 = PH[2 * kc][1];
            unsigned a2 = PH[2 * kc + 1][0], a3 = PH[2 * kc + 1][1];
            #pragma unroll
            for (int ndp = 0; ndp < 2; ndp++) {
                unsigned bv[4];
                unsigned off = A_V0 + cbuf + (16 * ndp + vrow) * VSTR + 16 * kc + vcolp;
                ldsm4(bv, sbase + off * 2);
                mma16816(O[2 * ndp],     a0, a1, a2, a3, bv[0], bv[1]);
                mma16816(O[2 * ndp + 1], a0, a1, a2, a3, bv[2], bv[3]);
            }
        }

        __syncthreads();   // single barrier: buf[cur] reads + buf[next] writes done
    }

    // ---- finalize: row sums over quad lanes, normalize, write ---------
    const float LN2 = 0.6931471805599453f;
    float lg, tg, lh, th, tmp;
    upk2(l2g, lg, tmp); lg += tmp;
    upk2(t2g, tg, tmp); tg += tmp;
    upk2(l2h, lh, tmp); lh += tmp;
    upk2(t2h, th, tmp); th += tmp;
    #pragma unroll
    for (int off = 1; off <= 2; off <<= 1) {
        lg += __shfl_xor_sync(0xFFFFFFFFu, lg, off);
        tg += __shfl_xor_sync(0xFFFFFFFFu, tg, off);
        lh += __shfl_xor_sync(0xFFFFFFFFu, lh, off);
        th += __shfl_xor_sync(0xFFFFFFFFu, th, off);
    }
    float inv0 = 1.0f / lg;
    float inv1 = 1.0f / lh;

    float* obase = g_att + ((size_t)b * HID_ + h * DH_) * HW_;
    const int row0 = m0 + 16 * w + g;
    const int row1 = row0 + 8;
    #pragma unroll
    for (int ntd = 0; ntd < 4; ntd++) {
        int d = 8 * ntd + 2 * qt;
        obase[(size_t)d * HW_ + row0]       = O[ntd][0] * inv0;
        obase[(size_t)(d + 1) * HW_ + row0] = O[ntd][1] * inv0;
        obase[(size_t)d * HW_ + row1]       = O[ntd][2] * inv1;
        obase[(size_t)(d + 1) * HW_ + row1] = O[ntd][3] * inv1;
    }

    float ev = 0.0f;
    if (qt == 0)
        ev = (tg * LN2 * inv0 - logf(lg)) + (th * LN2 * inv1 - logf(lh));
    __syncthreads();
    block_accum(ev, 1, red);
}

__global__ void zero_acc_kernel() {
    if (threadIdx.x < 3) g_acc[threadIdx.x] = 0.0;
}

// Empty marker so the ncu capture slot lands on attn_kernel.
__global__ void marker_kernel() {}

__global__ void energy_kernel(float* __restrict__ out, int out_size) {
    if (out_size > NOUT) {
        double e = -0.5 * g_acc[0] + g_acc[1] - 0.5 * g_acc[2];
        out[NOUT] = (float)e;
    }
}

extern "C" void kernel_launch(void* const* d_in, const int* in_sizes, int n_in,
                              void* d_out, int out_size)
{
    const float* x     = (const float*)d_in[0];
    const float* w_qkv = (const float*)d_in[1];
    const float* b_qkv = (const float*)d_in[2];
    const float* w_out = (const float*)d_in[3];
    const float* b_out = (const float*)d_in[4];
    float* out = (float*)d_out;

    void *pqkv = nullptr, *patt = nullptr;
    cudaGetSymbolAddress(&pqkv, g_qkv);
    cudaGetSymbolAddress(&patt, g_att);

    zero_acc_kernel<<<1, 32>>>();
    tc_gemm_kernel<<<dim3(HW_ / 128, QKV_ / 128, B_), 256>>>(
        w_qkv, x, b_qkv, (float*)pqkv, QKV_, C_, 0);
    marker_kernel<<<1, 32>>>();
    attn_kernel<<<dim3(HW_ / MT, B_ * HEADS_), 256>>>();
    tc_gemm_kernel<<<dim3(HW_ / 128, C_ / 128, B_), 256>>>(
        w_out, (const float*)patt, b_out, out, C_, HID_, 2);
    energy_kernel<<<1, 1>>>(out, out_size);
}

// round 16
// speedup vs baseline: 1.6918x; 1.0874x over previous
#include <cuda_runtime.h>
#include <cuda_fp16.h>
#include <math.h>

#define B_    8
#define C_    256
#define HW_   2304
#define HEADS_ 4
#define DH_   32
#define HID_  128
#define QKV_  384
#define NOUT  (B_*C_*HW_)   // 4718592

// Attention tiling: 128 query rows/CTA, 36 key tiles of 64
#define MT 128
#define NT 64
#define NTILES (HW_/NT)

// SMEM half-element offsets (padded strides for conflict-free ldmatrix)
#define QSTR 40     // 32 halfs data + 8 pad  (80B row)
#define VSTR 72     // 64 halfs data + 8 pad  (144B row)
// K and V both stored [d][j] (source orientation); K consumed via ldmatrix.trans.
#define A_QH 0                        // Q hi: 128 x 40 = 5120
#define A_K0 (A_QH + MT*QSTR)         // 5120
#define A_V0 (A_K0 + DH_*VSTR)        // 7424
#define A_BSTR (2*DH_*VSTR)           // 4608 halfs per buffer (K+V)
#define A_HALFS (A_K0 + 2*A_BSTR)     // 14336 halfs = 28672 B

// tc_gemm SMEM layout (halfs): W-hi, W-lo (128 m x 40), X-hi (128 n x 40)
#define G_WH 0
#define G_WL 5120
#define G_XH 10240
#define G_HALFS 15360                 // 30720 B

typedef unsigned long long ull;

// Scratch (static device globals: allowed; allocs are not) — fp16 now.
__device__ __half g_qkv_h[B_*QKV_*HW_];   // [b][384][2304] (n fast)
__device__ __half g_att_h[B_*HW_*HID_];   // [b][hw][128]   (channel fast)
__device__ double g_acc[3];               // [sumsq_qkv, e_attn, sumsq_out]

// ---------------- packed f32x2 helpers (Blackwell FFMA2) -------------------
__device__ __forceinline__ ull pk2(float lo, float hi) {
    ull r; asm("mov.b64 %0, {%1,%2};" : "=l"(r) : "f"(lo), "f"(hi)); return r;
}
__device__ __forceinline__ void upk2(ull v, float& lo, float& hi) {
    asm("mov.b64 {%0,%1}, %2;" : "=f"(lo), "=f"(hi) : "l"(v));
}
__device__ __forceinline__ ull fma2(ull a, ull b, ull c) {
    ull d; asm("fma.rn.f32x2 %0, %1, %2, %3;" : "=l"(d) : "l"(a), "l"(b), "l"(c));
    return d;
}
__device__ __forceinline__ ull add2(ull a, ull b) {
    ull d; asm("add.rn.f32x2 %0, %1, %2;" : "=l"(d) : "l"(a), "l"(b));
    return d;
}

// ---------------- fp16 pack/unpack + MUFU exp2 -----------------------------
__device__ __forceinline__ unsigned f2h2(float lo, float hi) {
    unsigned u;  // PTX cvt: first source -> HIGH half
    asm("cvt.rn.f16x2.f32 %0, %1, %2;" : "=r"(u) : "f"(hi), "f"(lo));
    return u;
}
__device__ __forceinline__ void h2tof(unsigned u, float& lo, float& hi) {
    asm("{.reg .b16 l, h;\n\t mov.b32 {l, h}, %2;\n\t"
        "cvt.f32.f16 %0, l;\n\t cvt.f32.f16 %1, h;}"
        : "=f"(lo), "=f"(hi) : "r"(u));
}
__device__ __forceinline__ unsigned ex2h2(unsigned y) {
    unsigned p; asm("ex2.approx.f16x2 %0, %1;" : "=r"(p) : "r"(y));
    return p;
}

// ---------------- mma.sync + ldmatrix (sm_80 path; no 'a'-gated features) --
__device__ __forceinline__ void mma16816(float* c,
    unsigned a0, unsigned a1, unsigned a2, unsigned a3,
    unsigned b0, unsigned b1)
{
    asm volatile(
        "mma.sync.aligned.m16n8k16.row.col.f32.f16.f16.f32 "
        "{%0,%1,%2,%3}, {%4,%5,%6,%7}, {%8,%9}, {%0,%1,%2,%3};"
        : "+f"(c[0]), "+f"(c[1]), "+f"(c[2]), "+f"(c[3])
        : "r"(a0), "r"(a1), "r"(a2), "r"(a3), "r"(b0), "r"(b1));
}
__device__ __forceinline__ void ldsm4(unsigned* r, unsigned addr) {
    asm volatile("ldmatrix.sync.aligned.m8n8.x4.shared.b16 {%0,%1,%2,%3}, [%4];"
        : "=r"(r[0]), "=r"(r[1]), "=r"(r[2]), "=r"(r[3]) : "r"(addr));
}
__device__ __forceinline__ void ldsm4t(unsigned* r, unsigned addr) {
    asm volatile("ldmatrix.sync.aligned.m8n8.x4.trans.shared.b16 {%0,%1,%2,%3}, [%4];"
        : "=r"(r[0]), "=r"(r[1]), "=r"(r[2]), "=r"(r[3]) : "r"(addr));
}

// Block-reduce a float and atomically add (as double) into g_acc[idx].
__device__ __forceinline__ void block_accum(float v, int idx, float* red) {
    #pragma unroll
    for (int off = 16; off > 0; off >>= 1)
        v += __shfl_down_sync(0xFFFFFFFFu, v, off);
    int lane = threadIdx.x & 31, warp = threadIdx.x >> 5;
    if (lane == 0) red[warp] = v;
    __syncthreads();
    if (warp == 0) {
        int nw = (blockDim.x + 31) >> 5;
        float s = (lane < nw) ? red[lane] : 0.0f;
        #pragma unroll
        for (int off = 4; off > 0; off >>= 1)
            s += __shfl_down_sync(0xFFFFFFFFu, s, off);
        if (lane == 0) atomicAdd(&g_acc[idx], (double)s);
    }
}

// ---------------------------------------------------------------------------
// QKV GEMM: Ch[b,m,n] = half( sum_k Wt[m,k]*X[b,k,n] + bias[m] )
// fp32 input x, fp16 OUTPUT (consumer-identical rounding; sumsq in fp32).
// 2-pass fp16 split on W. Grid: (HW_/128, QKV_/128, B_), 256 threads.
// ---------------------------------------------------------------------------
__global__ void __launch_bounds__(256, 2)
tc_gemm_qkv_kernel(const float* __restrict__ Wt, const float* __restrict__ X,
                   const float* __restrict__ bias, __half* __restrict__ Cdst)
{
    const int K = C_;
    __shared__ __align__(16) __half smh[G_HALFS];
    __shared__ float red[8];

    const int tid  = threadIdx.x;
    const int lane = tid & 31;
    const int w    = tid >> 5;
    const int lr   = lane & 7;
    const int sel  = lane >> 3;
    const int g    = lane >> 2;
    const int qt   = lane & 3;

    const int bz = blockIdx.z;
    const int m0 = blockIdx.y * 128;
    const int n0 = blockIdx.x * 128;
    const float* Xb = X + (size_t)bz * K * HW_;

    const unsigned sbase = (unsigned)__cvta_generic_to_shared(smh);

    float C[16][4] = {};

    const int krow  = lr + 8 * (sel >> 1);
    const int kcolp = 8 * (sel & 1);
    const int arow  = 16 * w + lr + 8 * (sel & 1);
    const int acolp = 8 * (sel >> 1);

    for (int k0 = 0; k0 < K; k0 += 32) {
        __syncthreads();
        // ---- W chunk: 128 m x 32 k, split hi/lo ----
        {
            const int m = tid >> 1;
            const int khw = (tid & 1) * 16;
            const float4* wrow = (const float4*)(Wt + (size_t)(m0 + m) * K + k0 + khw);
            #pragma unroll
            for (int r4 = 0; r4 < 4; r4++) {
                float4 wv = wrow[r4];
                unsigned hp0 = f2h2(wv.x, wv.y);
                unsigned hp1 = f2h2(wv.z, wv.w);
                float rx, ry, rz, rw;
                h2tof(hp0, rx, ry);
                h2tof(hp1, rz, rw);
                unsigned lp0 = f2h2(wv.x - rx, wv.y - ry);
                unsigned lp1 = f2h2(wv.z - rz, wv.w - rw);
                int base = m * QSTR + khw + 4 * r4;
                *(unsigned*)&smh[G_WH + base]     = hp0;
                *(unsigned*)&smh[G_WH + base + 2] = hp1;
                *(unsigned*)&smh[G_WL + base]     = lp0;
                *(unsigned*)&smh[G_WL + base + 2] = lp1;
            }
        }
        // ---- X chunk: 128 n x 32 k (transposed store), hi only ----
        {
            const int n = tid & 127;
            const int khx = (tid >> 7) * 16;
            #pragma unroll
            for (int r = 0; r < 16; r++) {
                float xf = Xb[(size_t)(k0 + khx + r) * HW_ + n0 + n];
                smh[G_XH + n * QSTR + khx + r] = __float2half_rn(xf);
            }
        }
        __syncthreads();

        // ---- A frags (hi+lo), then MMA over 16 n-blocks ----
        #pragma unroll
        for (int s = 0; s < 2; s++) {
            unsigned ah[4], al[4];
            ldsm4(ah, sbase + (G_WH + arow * QSTR + 16 * s + acolp) * 2);
            ldsm4(al, sbase + (G_WL + arow * QSTR + 16 * s + acolp) * 2);
            #pragma unroll
            for (int nbp = 0; nbp < 8; nbp++) {
                unsigned bv[4];
                int off = G_XH + (16 * nbp + krow) * QSTR + 16 * s + kcolp;
                ldsm4(bv, sbase + off * 2);
                mma16816(C[2 * nbp],     ah[0], ah[1], ah[2], ah[3], bv[0], bv[1]);
                mma16816(C[2 * nbp + 1], ah[0], ah[1], ah[2], ah[3], bv[2], bv[3]);
                mma16816(C[2 * nbp],     al[0], al[1], al[2], al[3], bv[0], bv[1]);
                mma16816(C[2 * nbp + 1], al[0], al[1], al[2], al[3], bv[2], bv[3]);
            }
        }
    }

    // ---- epilogue: bias, fp32 sumsq, fp16 packed store ----
    const int row0 = m0 + 16 * w + g;
    const int row1 = row0 + 8;
    const float b0 = bias[row0];
    const float b1 = bias[row1];
    __half* c0 = Cdst + ((size_t)bz * QKV_ + row0) * HW_ + n0;
    __half* c1 = Cdst + ((size_t)bz * QKV_ + row1) * HW_ + n0;
    float ss = 0.0f;
    #pragma unroll
    for (int nb = 0; nb < 16; nb++) {
        int n = 8 * nb + 2 * qt;
        float v0 = C[nb][0] + b0;
        float v1 = C[nb][1] + b0;
        float v2 = C[nb][2] + b1;
        float v3 = C[nb][3] + b1;
        *(unsigned*)&c0[n] = f2h2(v0, v1);
        *(unsigned*)&c1[n] = f2h2(v2, v3);
        ss = fmaf(v0, v0, ss); ss = fmaf(v1, v1, ss);
        ss = fmaf(v2, v2, ss); ss = fmaf(v3, v3, ss);
    }
    __syncthreads();
    block_accum(ss, 0, red);
}

// ---------------------------------------------------------------------------
// OUT GEMM: C[b,m,n] = sum_k Wt[m,k]*Xh[b,n,k] + bias[m], fp32 output.
// Xh is g_att_h in [hw][hid] layout (channel fast) -> vectorized staging.
// Grid: (HW_/128, C_/128, B_), 256 threads. Sumsq -> g_acc[2].
// ---------------------------------------------------------------------------
__global__ void __launch_bounds__(256, 2)
tc_gemm_out_kernel(const float* __restrict__ Wt, const __half* __restrict__ Xh,
                   const float* __restrict__ bias, float* __restrict__ Cdst)
{
    const int K = HID_;
    __shared__ __align__(16) __half smh[G_HALFS];
    __shared__ float red[8];

    const int tid  = threadIdx.x;
    const int lane = tid & 31;
    const int w    = tid >> 5;
    const int lr   = lane & 7;
    const int sel  = lane >> 3;
    const int g    = lane >> 2;
    const int qt   = lane & 3;

    const int bz = blockIdx.z;
    const int m0 = blockIdx.y * 128;
    const int n0 = blockIdx.x * 128;
    const __half* Xb = Xh + (size_t)bz * HW_ * HID_;

    const unsigned sbase = (unsigned)__cvta_generic_to_shared(smh);

    float C[16][4] = {};

    const int krow  = lr + 8 * (sel >> 1);
    const int kcolp = 8 * (sel & 1);
    const int arow  = 16 * w + lr + 8 * (sel & 1);
    const int acolp = 8 * (sel >> 1);

    for (int k0 = 0; k0 < K; k0 += 32) {
        __syncthreads();
        // ---- W chunk: 128 m x 32 k, split hi/lo ----
        {
            const int m = tid >> 1;
            const int khw = (tid & 1) * 16;
            const float4* wrow = (const float4*)(Wt + (size_t)(m0 + m) * K + k0 + khw);
            #pragma unroll
            for (int r4 = 0; r4 < 4; r4++) {
                float4 wv = wrow[r4];
                unsigned hp0 = f2h2(wv.x, wv.y);
                unsigned hp1 = f2h2(wv.z, wv.w);
                float rx, ry, rz, rw;
                h2tof(hp0, rx, ry);
                h2tof(hp1, rz, rw);
                unsigned lp0 = f2h2(wv.x - rx, wv.y - ry);
                unsigned lp1 = f2h2(wv.z - rz, wv.w - rw);
                int base = m * QSTR + khw + 4 * r4;
                *(unsigned*)&smh[G_WH + base]     = hp0;
                *(unsigned*)&smh[G_WH + base + 2] = hp1;
                *(unsigned*)&smh[G_WL + base]     = lp0;
                *(unsigned*)&smh[G_WL + base + 2] = lp1;
            }
        }
        // ---- X chunk: 128 n x 32 k, fp16 vectorized (channel-fast src) ----
        {
            const int n = tid & 127;
            const int khx = (tid >> 7) * 16;
            const uint4* xp = (const uint4*)(Xb + (size_t)(n0 + n) * HID_ + k0 + khx);
            uint4 x0 = xp[0], x1 = xp[1];
            *(uint4*)&smh[G_XH + n * QSTR + khx]     = x0;
            *(uint4*)&smh[G_XH + n * QSTR + khx + 8] = x1;
        }
        __syncthreads();

        // ---- A frags (hi+lo), then MMA over 16 n-blocks ----
        #pragma unroll
        for (int s = 0; s < 2; s++) {
            unsigned ah[4], al[4];
            ldsm4(ah, sbase + (G_WH + arow * QSTR + 16 * s + acolp) * 2);
            ldsm4(al, sbase + (G_WL + arow * QSTR + 16 * s + acolp) * 2);
            #pragma unroll
            for (int nbp = 0; nbp < 8; nbp++) {
                unsigned bv[4];
                int off = G_XH + (16 * nbp + krow) * QSTR + 16 * s + kcolp;
                ldsm4(bv, sbase + off * 2);
                mma16816(C[2 * nbp],     ah[0], ah[1], ah[2], ah[3], bv[0], bv[1]);
                mma16816(C[2 * nbp + 1], ah[0], ah[1], ah[2], ah[3], bv[2], bv[3]);
                mma16816(C[2 * nbp],     al[0], al[1], al[2], al[3], bv[0], bv[1]);
                mma16816(C[2 * nbp + 1], al[0], al[1], al[2], al[3], bv[2], bv[3]);
            }
        }
    }

    // ---- epilogue: bias, store fp32, sumsq ----
    const int row0 = m0 + 16 * w + g;
    const int row1 = row0 + 8;
    const float b0 = bias[row0];
    const float b1 = bias[row1];
    float* c0 = Cdst + ((size_t)bz * C_ + row0) * HW_ + n0;
    float* c1 = Cdst + ((size_t)bz * C_ + row1) * HW_ + n0;
    float ss = 0.0f;
    #pragma unroll
    for (int nb = 0; nb < 16; nb++) {
        int n = 8 * nb + 2 * qt;
        float v0 = C[nb][0] + b0;
        float v1 = C[nb][1] + b0;
        float v2 = C[nb][2] + b1;
        float v3 = C[nb][3] + b1;
        c0[n] = v0; c0[n + 1] = v1;
        c1[n] = v2; c1[n + 1] = v3;
        ss = fmaf(v0, v0, ss); ss = fmaf(v1, v1, ss);
        ss = fmaf(v2, v2, ss); ss = fmaf(v3, v3, ss);
    }
    __syncthreads();
    block_accum(ss, 2, red);
}

// ---------------------------------------------------------------------------
// Tensor-core flash attention: fp16 in / fp16 out, double-buffered, MUFU
// softmax. K/V staged with 1 LDG.128 + 1 STS.128 per thread (no converts:
// producer already wrote fp16). Output to g_att_h [hw][hid] via packed u32.
// Grid: (HW_/128, B_*HEADS_). e_attn -> g_acc[1].
// ---------------------------------------------------------------------------
__global__ void __launch_bounds__(256, 2)
attn_kernel()
{
    __shared__ __align__(16) __half smh[A_HALFS];
    __shared__ float red[8];

    const int tid  = threadIdx.x;
    const int lane = tid & 31;
    const int w    = tid >> 5;
    const int lr   = lane & 7;
    const int sel  = lane >> 3;
    const int g    = lane >> 2;
    const int qt   = lane & 3;

    const int bh = blockIdx.y, b = bh >> 2, h = bh & 3;
    const int m0 = blockIdx.x * MT;

    const __half* qb = g_qkv_h + ((size_t)b*QKV_ +            h*DH_) * HW_;
    const __half* kb = g_qkv_h + ((size_t)b*QKV_ + HID_     + h*DH_) * HW_;
    const __half* vb = g_qkv_h + ((size_t)b*QKV_ + 2*HID_   + h*DH_) * HW_;

    const unsigned sbase = (unsigned)__cvta_generic_to_shared(smh);

    // ---- load Q (fp16 direct copy) ------------------------------------
    {
        const int i = tid & 127;
        const int dg = tid >> 7;          // 0 or 1
        #pragma unroll
        for (int r = 0; r < 16; r++) {
            int d = dg * 16 + r;
            smh[A_QH + i * QSTR + d] = qb[(size_t)d * HW_ + m0 + i];
        }
    }

    // staging mapping (K and V identical): row d = tid>>3, 8 consecutive j
    const int sd  = tid >> 3;            // 0..31
    const int sj0 = (tid & 7) * 8;       // 0..56

    // ---- prologue: tile0 -> buf0; tile1 -> regs -----------------------
    uint4 kq, vq;
    {
        kq = *(const uint4*)(kb + (size_t)sd * HW_ + sj0);
        vq = *(const uint4*)(vb + (size_t)sd * HW_ + sj0);
        *(uint4*)&smh[A_K0 + sd * VSTR + sj0] = kq;
        *(uint4*)&smh[A_V0 + sd * VSTR + sj0] = vq;
    }
    kq = *(const uint4*)(kb + (size_t)sd * HW_ + NT + sj0);
    vq = *(const uint4*)(vb + (size_t)sd * HW_ + NT + sj0);
    __syncthreads();

    // ---- resident Q A-frags: aq[kchunk][4] ----------------------------
    unsigned aq[2][4];
    {
        int qrow = 16 * w + lr + 8 * (sel & 1);
        #pragma unroll
        for (int c = 0; c < 2; c++)
            ldsm4(aq[c], sbase + (A_QH + qrow * QSTR + 16 * c + 8 * (sel >> 1)) * 2);
    }

    // scale * log2(e): softmax in log2 domain, |y| <= ~0.4
    const float SCL = 0.17677669529663687f * 1.4426950408889634f;

    float O[4][4] = {};                 // 16 rows x 32 d, fp32, lives all tiles
    ull l2g = 0, t2g = 0, l2h = 0, t2h = 0;

    // S b-frag (trans): k-row = 16*cc + 8*(sel&1) + lr, n off = 16*ntp + 8*(sel>>1)
    const int tkrow = 8 * (sel & 1) + lr;
    const int tncol = 8 * (sel >> 1);
    // PV b-frag (non-trans, V rows = d = n): row = lr + 8*(sel>>1), col k = j
    const int vrow  = lr + 8 * (sel >> 1);
    const int vcolp = 8 * (sel & 1);

    for (int tile = 0; tile < NTILES; tile++) {
        const unsigned cbuf = (tile & 1) ? A_BSTR : 0u;   // read buffer offset
        const unsigned nbuf = (tile & 1) ? 0u : A_BSTR;   // write buffer offset

        // ---- commit prefetched tile t+1 into the other buffer ---------
        if (tile + 1 < NTILES) {
            *(uint4*)&smh[A_K0 + nbuf + sd * VSTR + sj0] = kq;
            *(uint4*)&smh[A_V0 + nbuf + sd * VSTR + sj0] = vq;
        }
        // ---- prefetch tile t+2 (LDGs overlap the MMAs below) ----------
        if (tile + 2 < NTILES) {
            const int jn = (tile + 2) * NT + sj0;
            kq = *(const uint4*)(kb + (size_t)sd * HW_ + jn);
            vq = *(const uint4*)(vb + (size_t)sd * HW_ + jn);
        }

        // ---- S = qh*kh (K via ldmatrix.trans from [d][j] storage) -----
        float sC[8][4] = {};
        #pragma unroll
        for (int cc = 0; cc < 2; cc++) {
            #pragma unroll
            for (int ntp = 0; ntp < 4; ntp++) {
                unsigned bv[4];
                unsigned off = A_K0 + cbuf + (16 * cc + tkrow) * VSTR + 16 * ntp + tncol;
                ldsm4t(bv, sbase + off * 2);
                mma16816(sC[2 * ntp],     aq[cc][0], aq[cc][1], aq[cc][2], aq[cc][3], bv[0], bv[1]);
                mma16816(sC[2 * ntp + 1], aq[cc][0], aq[cc][1], aq[cc][2], aq[cc][3], bv[2], bv[3]);
            }
        }

        // ---- softmax: p = ex2(y), y = s*SCL (log2 domain), via MUFU ---
        unsigned PH[8][2];
        #pragma unroll
        for (int nt = 0; nt < 8; nt++) {
            // rows g
            float y0 = sC[nt][0] * SCL;
            float y1 = sC[nt][1] * SCL;
            unsigned ph = ex2h2(f2h2(y0, y1));
            PH[nt][0] = ph;
            float p0, p1; h2tof(ph, p0, p1);
            ull p2 = pk2(p0, p1);
            t2g = fma2(p2, pk2(y0, y1), t2g);
            l2g = add2(l2g, p2);
            // rows g+8
            y0 = sC[nt][2] * SCL;
            y1 = sC[nt][3] * SCL;
            ph = ex2h2(f2h2(y0, y1));
            PH[nt][1] = ph;
            h2tof(ph, p0, p1);
            p2 = pk2(p0, p1);
            t2h = fma2(p2, pk2(y0, y1), t2h);
            l2h = add2(l2h, p2);
        }

        // ---- O += ph*vh (V non-trans, rows = d) -----------------------
        #pragma unroll
        for (int kc = 0; kc < 4; kc++) {
            unsigned a0 = PH[2 * kc][0],     a1 = PH[2 * kc][1];
            unsigned a2 = PH[2 * kc + 1][0], a3 = PH[2 * kc + 1][1];
            #pragma unroll
            for (int ndp = 0; ndp < 2; ndp++) {
                unsigned bv[4];
                unsigned off = A_V0 + cbuf + (16 * ndp + vrow) * VSTR + 16 * kc + vcolp;
                ldsm4(bv, sbase + off * 2);
                mma16816(O[2 * ndp],     a0, a1, a2, a3, bv[0], bv[1]);
                mma16816(O[2 * ndp + 1], a0, a1, a2, a3, bv[2], bv[3]);
            }
        }

        __syncthreads();   // single barrier: buf[cur] reads + buf[next] writes done
    }

    // ---- finalize: row sums over quad lanes, normalize, write fp16 ----
    const float LN2 = 0.6931471805599453f;
    float lg, tg, lh, th, tmp;
    upk2(l2g, lg, tmp); lg += tmp;
    upk2(t2g, tg, tmp); tg += tmp;
    upk2(l2h, lh, tmp); lh += tmp;
    upk2(t2h, th, tmp); th += tmp;
    #pragma unroll
    for (int off = 1; off <= 2; off <<= 1) {
        lg += __shfl_xor_sync(0xFFFFFFFFu, lg, off);
        tg += __shfl_xor_sync(0xFFFFFFFFu, tg, off);
        lh += __shfl_xor_sync(0xFFFFFFFFu, lh, off);
        th += __shfl_xor_sync(0xFFFFFFFFu, th, off);
    }
    float inv0 = 1.0f / lg;
    float inv1 = 1.0f / lh;

    // g_att_h layout: [b][hw][128], channel = h*32 + d (d even pairs -> u32)
    __half* obase = g_att_h + (size_t)b * HW_ * HID_ + h * DH_;
    const int row0 = m0 + 16 * w + g;
    const int row1 = row0 + 8;
    #pragma unroll
    for (int ntd = 0; ntd < 4; ntd++) {
        int d = 8 * ntd + 2 * qt;
        *(unsigned*)&obase[(size_t)row0 * HID_ + d] = f2h2(O[ntd][0] * inv0, O[ntd][1] * inv0);
        *(unsigned*)&obase[(size_t)row1 * HID_ + d] = f2h2(O[ntd][2] * inv1, O[ntd][3] * inv1);
    }

    float ev = 0.0f;
    if (qt == 0)
        ev = (tg * LN2 * inv0 - logf(lg)) + (th * LN2 * inv1 - logf(lh));
    __syncthreads();
    block_accum(ev, 1, red);
}

__global__ void zero_acc_kernel() {
    if (threadIdx.x < 3) g_acc[threadIdx.x] = 0.0;
}

// Empty marker so the ncu capture slot lands on attn_kernel.
__global__ void marker_kernel() {}

__global__ void energy_kernel(float* __restrict__ out, int out_size) {
    if (out_size > NOUT) {
        double e = -0.5 * g_acc[0] + g_acc[1] - 0.5 * g_acc[2];
        out[NOUT] = (float)e;
    }
}

extern "C" void kernel_launch(void* const* d_in, const int* in_sizes, int n_in,
                              void* d_out, int out_size)
{
    const float* x     = (const float*)d_in[0];
    const float* w_qkv = (const float*)d_in[1];
    const float* b_qkv = (const float*)d_in[2];
    const float* w_out = (const float*)d_in[3];
    const float* b_out = (const float*)d_in[4];
    float* out = (float*)d_out;

    void *pqkv = nullptr, *patt = nullptr;
    cudaGetSymbolAddress(&pqkv, g_qkv_h);
    cudaGetSymbolAddress(&patt, g_att_h);

    zero_acc_kernel<<<1, 32>>>();
    tc_gemm_qkv_kernel<<<dim3(HW_ / 128, QKV_ / 128, B_), 256>>>(
        w_qkv, x, b_qkv, (__half*)pqkv);
    marker_kernel<<<1, 32>>>();
    attn_kernel<<<dim3(HW_ / MT, B_ * HEADS_), 256>>>();
    tc_gemm_out_kernel<<<dim3(HW_ / 128, C_ / 128, B_), 256>>>(
        w_out, (const __half*)patt, b_out, out);
    energy_kernel<<<1, 1>>>(out, out_size);
}

// round 17
// speedup vs baseline: 1.7085x; 1.0099x over previous
#include <cuda_runtime.h>
#include <cuda_fp16.h>
#include <math.h>

#define B_    8
#define C_    256
#define HW_   2304
#define HEADS_ 4
#define DH_   32
#define HID_  128
#define QKV_  384
#define NOUT  (B_*C_*HW_)   // 4718592

// Attention tiling: 128 query rows/CTA, 36 key tiles of 64
#define MT 128
#define NT 64
#define NTILES (HW_/NT)

// SMEM half-element offsets (padded strides for conflict-free ldmatrix)
#define QSTR 40     // 32 halfs data + 8 pad  (80B row)
#define VSTR 72     // 64 halfs data + 8 pad  (144B row)
#define A_QH 0                        // Q: 128 x 40 = 5120
#define A_K0 (A_QH + MT*QSTR)         // 5120
#define A_V0 (A_K0 + DH_*VSTR)        // 7424
#define A_BSTR (2*DH_*VSTR)           // 4608 halfs per buffer (K+V)
#define A_HALFS (A_K0 + 2*A_BSTR)     // 14336 halfs = 28672 B

// GEMM SMEM layouts (halfs)
#define XSTR 136    // 128 halfs data + 8 pad (272B row) for [k][n] X tile
#define G_WH 0                        // W hi: 128 x 40
#define G_WL 5120                     // W lo: 128 x 40
#define G_XQ 10240                    // qkv X: 32 x 136 = 4352 -> 14592 total
#define G_XO 10240                    // out X: 128 x 40 = 5120 -> 15360 total
#define G_HALFS 15360

typedef unsigned long long ull;

// Scratch (static device globals: allowed; allocs are not)
__device__ __half g_qkv_h[B_*QKV_*HW_];   // [b][384][2304] (n fast)
__device__ __half g_att_h[B_*HW_*HID_];   // [b][hw][128]   (channel fast)
__device__ __half g_wh[QKV_*C_ + C_*HID_]; // precomputed W hi (qkv | out)
__device__ __half g_wl[QKV_*C_ + C_*HID_]; // precomputed W lo
__device__ double g_acc[3];               // [sumsq_qkv, e_attn, sumsq_out]
#define WOFF_OUT (QKV_*C_)

// ---------------- packed f32x2 helpers (Blackwell FFMA2) -------------------
__device__ __forceinline__ ull pk2(float lo, float hi) {
    ull r; asm("mov.b64 %0, {%1,%2};" : "=l"(r) : "f"(lo), "f"(hi)); return r;
}
__device__ __forceinline__ void upk2(ull v, float& lo, float& hi) {
    asm("mov.b64 {%0,%1}, %2;" : "=f"(lo), "=f"(hi) : "l"(v));
}
__device__ __forceinline__ ull fma2(ull a, ull b, ull c) {
    ull d; asm("fma.rn.f32x2 %0, %1, %2, %3;" : "=l"(d) : "l"(a), "l"(b), "l"(c));
    return d;
}
__device__ __forceinline__ ull add2(ull a, ull b) {
    ull d; asm("add.rn.f32x2 %0, %1, %2;" : "=l"(d) : "l"(a), "l"(b));
    return d;
}

// ---------------- fp16 pack/unpack + MUFU exp2 -----------------------------
__device__ __forceinline__ unsigned f2h2(float lo, float hi) {
    unsigned u;  // PTX cvt: first source -> HIGH half
    asm("cvt.rn.f16x2.f32 %0, %1, %2;" : "=r"(u) : "f"(hi), "f"(lo));
    return u;
}
__device__ __forceinline__ void h2tof(unsigned u, float& lo, float& hi) {
    asm("{.reg .b16 l, h;\n\t mov.b32 {l, h}, %2;\n\t"
        "cvt.f32.f16 %0, l;\n\t cvt.f32.f16 %1, h;}"
        : "=f"(lo), "=f"(hi) : "r"(u));
}
__device__ __forceinline__ unsigned ex2h2(unsigned y) {
    unsigned p; asm("ex2.approx.f16x2 %0, %1;" : "=r"(p) : "r"(y));
    return p;
}

// ---------------- mma.sync + ldmatrix (sm_80 path; no 'a'-gated features) --
__device__ __forceinline__ void mma16816(float* c,
    unsigned a0, unsigned a1, unsigned a2, unsigned a3,
    unsigned b0, unsigned b1)
{
    asm volatile(
        "mma.sync.aligned.m16n8k16.row.col.f32.f16.f16.f32 "
        "{%0,%1,%2,%3}, {%4,%5,%6,%7}, {%8,%9}, {%0,%1,%2,%3};"
        : "+f"(c[0]), "+f"(c[1]), "+f"(c[2]), "+f"(c[3])
        : "r"(a0), "r"(a1), "r"(a2), "r"(a3), "r"(b0), "r"(b1));
}
__device__ __forceinline__ void ldsm4(unsigned* r, unsigned addr) {
    asm volatile("ldmatrix.sync.aligned.m8n8.x4.shared.b16 {%0,%1,%2,%3}, [%4];"
        : "=r"(r[0]), "=r"(r[1]), "=r"(r[2]), "=r"(r[3]) : "r"(addr));
}
__device__ __forceinline__ void ldsm4t(unsigned* r, unsigned addr) {
    asm volatile("ldmatrix.sync.aligned.m8n8.x4.trans.shared.b16 {%0,%1,%2,%3}, [%4];"
        : "=r"(r[0]), "=r"(r[1]), "=r"(r[2]), "=r"(r[3]) : "r"(addr));
}

// Block-reduce a float and atomically add (as double) into g_acc[idx].
__device__ __forceinline__ void block_accum(float v, int idx, float* red) {
    #pragma unroll
    for (int off = 16; off > 0; off >>= 1)
        v += __shfl_down_sync(0xFFFFFFFFu, v, off);
    int lane = threadIdx.x & 31, warp = threadIdx.x >> 5;
    if (lane == 0) red[warp] = v;
    __syncthreads();
    if (warp == 0) {
        int nw = (blockDim.x + 31) >> 5;
        float s = (lane < nw) ? red[lane] : 0.0f;
        #pragma unroll
        for (int off = 4; off > 0; off >>= 1)
            s += __shfl_down_sync(0xFFFFFFFFu, s, off);
        if (lane == 0) atomicAdd(&g_acc[idx], (double)s);
    }
}

// ---------------------------------------------------------------------------
// Prep: split both weight matrices into fp16 hi/lo once per launch.
// Also zeroes g_acc. Grid: 512 x 256.
// ---------------------------------------------------------------------------
__global__ void prep_kernel(const float* __restrict__ w_qkv,
                            const float* __restrict__ w_out)
{
    int idx = blockIdx.x * 256 + threadIdx.x;
    if (idx == 0) { g_acc[0] = 0.0; g_acc[1] = 0.0; g_acc[2] = 0.0; }
    float wv = (idx < WOFF_OUT) ? w_qkv[idx] : w_out[idx - WOFF_OUT];
    __half hv = __float2half_rn(wv);
    g_wh[idx] = hv;
    g_wl[idx] = __float2half_rn(wv - __half2float(hv));
}

// ---------------------------------------------------------------------------
// QKV GEMM: Ch[b,m,n] = half( sum_k Wt[m,k]*X[b,k,n] + bias[m] )
// W from precomputed fp16 hi/lo (vector copies). X staged [k][n] (conflict-
// free STS.128) and consumed via ldmatrix.trans (R15-verified pattern).
// Grid: (HW_/128, QKV_/128, B_), 256 threads. Sumsq -> g_acc[0].
// ---------------------------------------------------------------------------
__global__ void __launch_bounds__(256, 2)
tc_gemm_qkv_kernel(const float* __restrict__ X,
                   const float* __restrict__ bias, __half* __restrict__ Cdst)
{
    const int K = C_;
    __shared__ __align__(16) __half smh[G_HALFS];
    __shared__ float red[8];

    const int tid  = threadIdx.x;
    const int lane = tid & 31;
    const int w    = tid >> 5;
    const int lr   = lane & 7;
    const int sel  = lane >> 3;
    const int g    = lane >> 2;
    const int qt   = lane & 3;

    const int bz = blockIdx.z;
    const int m0 = blockIdx.y * 128;
    const int n0 = blockIdx.x * 128;
    const float* Xb = X + (size_t)bz * K * HW_;

    const unsigned sbase = (unsigned)__cvta_generic_to_shared(smh);

    float C[16][4] = {};

    const int arow  = 16 * w + lr + 8 * (sel & 1);
    const int acolp = 8 * (sel >> 1);
    const int tkrow = 8 * (sel & 1) + lr;      // trans b-frag k-row component
    const int tncol = 8 * (sel >> 1);          // trans b-frag n component

    // staging indices
    const int wm = tid >> 1, whk = (tid & 1) * 16;          // W: row m, 16 k
    const int xkr = tid >> 4, xn8 = (tid & 15) * 8;         // X: k-row, 8 n

    for (int k0 = 0; k0 < K; k0 += 32) {
        __syncthreads();
        // ---- W chunk: vector copy from precomputed hi/lo ----
        {
            const __half* whp = g_wh + (size_t)(m0 + wm) * K + k0 + whk;
            const __half* wlp = g_wl + (size_t)(m0 + wm) * K + k0 + whk;
            *(uint4*)&smh[G_WH + wm * QSTR + whk]     = *(const uint4*)whp;
            *(uint4*)&smh[G_WH + wm * QSTR + whk + 8] = *(const uint4*)(whp + 8);
            *(uint4*)&smh[G_WL + wm * QSTR + whk]     = *(const uint4*)wlp;
            *(uint4*)&smh[G_WL + wm * QSTR + whk + 8] = *(const uint4*)(wlp + 8);
        }
        // ---- X chunk: [k][n] tile, vectorized convert ----
        #pragma unroll
        for (int p = 0; p < 2; p++) {
            int row = xkr + 16 * p;
            const float4* xp = (const float4*)(Xb + (size_t)(k0 + row) * HW_ + n0 + xn8);
            float4 x0 = xp[0], x1 = xp[1];
            uint4 xq = make_uint4(f2h2(x0.x, x0.y), f2h2(x0.z, x0.w),
                                  f2h2(x1.x, x1.y), f2h2(x1.z, x1.w));
            *(uint4*)&smh[G_XQ + row * XSTR + xn8] = xq;
        }
        __syncthreads();

        // ---- A frags (hi+lo), B frags via ldsm4t on [k][n] ----
        #pragma unroll
        for (int s = 0; s < 2; s++) {
            unsigned ah[4], al[4];
            ldsm4(ah, sbase + (G_WH + arow * QSTR + 16 * s + acolp) * 2);
            ldsm4(al, sbase + (G_WL + arow * QSTR + 16 * s + acolp) * 2);
            #pragma unroll
            for (int nbp = 0; nbp < 8; nbp++) {
                unsigned bv[4];
                unsigned off = G_XQ + (16 * s + tkrow) * XSTR + 16 * nbp + tncol;
                ldsm4t(bv, sbase + off * 2);
                mma16816(C[2 * nbp],     ah[0], ah[1], ah[2], ah[3], bv[0], bv[1]);
                mma16816(C[2 * nbp + 1], ah[0], ah[1], ah[2], ah[3], bv[2], bv[3]);
                mma16816(C[2 * nbp],     al[0], al[1], al[2], al[3], bv[0], bv[1]);
                mma16816(C[2 * nbp + 1], al[0], al[1], al[2], al[3], bv[2], bv[3]);
            }
        }
    }

    // ---- epilogue: bias, fp32 sumsq, fp16 packed store ----
    const int row0 = m0 + 16 * w + g;
    const int row1 = row0 + 8;
    const float b0 = bias[row0];
    const float b1 = bias[row1];
    __half* c0 = Cdst + ((size_t)bz * QKV_ + row0) * HW_ + n0;
    __half* c1 = Cdst + ((size_t)bz * QKV_ + row1) * HW_ + n0;
    float ss = 0.0f;
    #pragma unroll
    for (int nb = 0; nb < 16; nb++) {
        int n = 8 * nb + 2 * qt;
        float v0 = C[nb][0] + b0;
        float v1 = C[nb][1] + b0;
        float v2 = C[nb][2] + b1;
        float v3 = C[nb][3] + b1;
        *(unsigned*)&c0[n] = f2h2(v0, v1);
        *(unsigned*)&c1[n] = f2h2(v2, v3);
        ss = fmaf(v0, v0, ss); ss = fmaf(v1, v1, ss);
        ss = fmaf(v2, v2, ss); ss = fmaf(v3, v3, ss);
    }
    __syncthreads();
    block_accum(ss, 0, red);
}

// ---------------------------------------------------------------------------
// OUT GEMM: C[b,m,n] = sum_k Wt[m,k]*Xh[b,n,k] + bias[m], fp32 output.
// W from precomputed fp16 hi/lo. Xh = g_att_h [hw][hid] -> vectorized copy,
// consumed via non-trans ldsm4 (rows = n), pattern passing since R9.
// Grid: (HW_/128, C_/128, B_), 256 threads. Sumsq -> g_acc[2].
// ---------------------------------------------------------------------------
__global__ void __launch_bounds__(256, 2)
tc_gemm_out_kernel(const __half* __restrict__ Xh,
                   const float* __restrict__ bias, float* __restrict__ Cdst)
{
    const int K = HID_;
    __shared__ __align__(16) __half smh[G_HALFS];
    __shared__ float red[8];

    const int tid  = threadIdx.x;
    const int lane = tid & 31;
    const int w    = tid >> 5;
    const int lr   = lane & 7;
    const int sel  = lane >> 3;
    const int g    = lane >> 2;
    const int qt   = lane & 3;

    const int bz = blockIdx.z;
    const int m0 = blockIdx.y * 128;
    const int n0 = blockIdx.x * 128;
    const __half* Xb = Xh + (size_t)bz * HW_ * HID_;

    const unsigned sbase = (unsigned)__cvta_generic_to_shared(smh);

    float C[16][4] = {};

    const int krow  = lr + 8 * (sel >> 1);
    const int kcolp = 8 * (sel & 1);
    const int arow  = 16 * w + lr + 8 * (sel & 1);
    const int acolp = 8 * (sel >> 1);

    const int wm = tid >> 1, whk = (tid & 1) * 16;

    for (int k0 = 0; k0 < K; k0 += 32) {
        __syncthreads();
        // ---- W chunk: vector copy from precomputed hi/lo ----
        {
            const __half* whp = g_wh + WOFF_OUT + (size_t)(m0 + wm) * K + k0 + whk;
            const __half* wlp = g_wl + WOFF_OUT + (size_t)(m0 + wm) * K + k0 + whk;
            *(uint4*)&smh[G_WH + wm * QSTR + whk]     = *(const uint4*)whp;
            *(uint4*)&smh[G_WH + wm * QSTR + whk + 8] = *(const uint4*)(whp + 8);
            *(uint4*)&smh[G_WL + wm * QSTR + whk]     = *(const uint4*)wlp;
            *(uint4*)&smh[G_WL + wm * QSTR + whk + 8] = *(const uint4*)(wlp + 8);
        }
        // ---- X chunk: 128 n x 32 k, fp16 vectorized (channel-fast src) ----
        {
            const int n = tid & 127;
            const int khx = (tid >> 7) * 16;
            const uint4* xp = (const uint4*)(Xb + (size_t)(n0 + n) * HID_ + k0 + khx);
            uint4 x0 = xp[0], x1 = xp[1];
            *(uint4*)&smh[G_XO + n * QSTR + khx]     = x0;
            *(uint4*)&smh[G_XO + n * QSTR + khx + 8] = x1;
        }
        __syncthreads();

        // ---- A frags (hi+lo), then MMA over 16 n-blocks ----
        #pragma unroll
        for (int s = 0; s < 2; s++) {
            unsigned ah[4], al[4];
            ldsm4(ah, sbase + (G_WH + arow * QSTR + 16 * s + acolp) * 2);
            ldsm4(al, sbase + (G_WL + arow * QSTR + 16 * s + acolp) * 2);
            #pragma unroll
            for (int nbp = 0; nbp < 8; nbp++) {
                unsigned bv[4];
                int off = G_XO + (16 * nbp + krow) * QSTR + 16 * s + kcolp;
                ldsm4(bv, sbase + off * 2);
                mma16816(C[2 * nbp],     ah[0], ah[1], ah[2], ah[3], bv[0], bv[1]);
                mma16816(C[2 * nbp + 1], ah[0], ah[1], ah[2], ah[3], bv[2], bv[3]);
                mma16816(C[2 * nbp],     al[0], al[1], al[2], al[3], bv[0], bv[1]);
                mma16816(C[2 * nbp + 1], al[0], al[1], al[2], al[3], bv[2], bv[3]);
            }
        }
    }

    // ---- epilogue: bias, store fp32, sumsq ----
    const int row0 = m0 + 16 * w + g;
    const int row1 = row0 + 8;
    const float b0 = bias[row0];
    const float b1 = bias[row1];
    float* c0 = Cdst + ((size_t)bz * C_ + row0) * HW_ + n0;
    float* c1 = Cdst + ((size_t)bz * C_ + row1) * HW_ + n0;
    float ss = 0.0f;
    #pragma unroll
    for (int nb = 0; nb < 16; nb++) {
        int n = 8 * nb + 2 * qt;
        float v0 = C[nb][0] + b0;
        float v1 = C[nb][1] + b0;
        float v2 = C[nb][2] + b1;
        float v3 = C[nb][3] + b1;
        c0[n] = v0; c0[n + 1] = v1;
        c1[n] = v2; c1[n + 1] = v3;
        ss = fmaf(v0, v0, ss); ss = fmaf(v1, v1, ss);
        ss = fmaf(v2, v2, ss); ss = fmaf(v3, v3, ss);
    }
    __syncthreads();
    block_accum(ss, 2, red);
}

// ---------------------------------------------------------------------------
// Tensor-core flash attention: fp16 in / fp16 out, double-buffered, MUFU
// softmax. Q pre-scaled by scale*log2e at staging, so the S MMA yields y
// directly (no per-element FMUL in the softmax hot loop).
// Grid: (HW_/128, B_*HEADS_). e_attn -> g_acc[1].
// ---------------------------------------------------------------------------
__global__ void __launch_bounds__(256, 2)
attn_kernel()
{
    __shared__ __align__(16) __half smh[A_HALFS];
    __shared__ float red[8];

    const int tid  = threadIdx.x;
    const int lane = tid & 31;
    const int w    = tid >> 5;
    const int lr   = lane & 7;
    const int sel  = lane >> 3;
    const int g    = lane >> 2;
    const int qt   = lane & 3;

    const int bh = blockIdx.y, b = bh >> 2, h = bh & 3;
    const int m0 = blockIdx.x * MT;

    const __half* qb = g_qkv_h + ((size_t)b*QKV_ +            h*DH_) * HW_;
    const __half* kb = g_qkv_h + ((size_t)b*QKV_ + HID_     + h*DH_) * HW_;
    const __half* vb = g_qkv_h + ((size_t)b*QKV_ + 2*HID_   + h*DH_) * HW_;

    const unsigned sbase = (unsigned)__cvta_generic_to_shared(smh);

    // scale * log2(e): softmax in log2 domain; folded into Q here.
    const float SCL = 0.17677669529663687f * 1.4426950408889634f;

    // ---- load Q (fp16, pre-scaled by SCL) ------------------------------
    {
        const int i = tid & 127;
        const int dg = tid >> 7;          // 0 or 1
        #pragma unroll
        for (int r = 0; r < 16; r++) {
            int d = dg * 16 + r;
            float qf = __half2float(qb[(size_t)d * HW_ + m0 + i]) * SCL;
            smh[A_QH + i * QSTR + d] = __float2half_rn(qf);
        }
    }

    // staging mapping (K and V identical): row d = tid>>3, 8 consecutive j
    const int sd  = tid >> 3;            // 0..31
    const int sj0 = (tid & 7) * 8;       // 0..56

    // ---- prologue: tile0 -> buf0; tile1 -> regs -----------------------
    uint4 kq, vq;
    {
        kq = *(const uint4*)(kb + (size_t)sd * HW_ + sj0);
        vq = *(const uint4*)(vb + (size_t)sd * HW_ + sj0);
        *(uint4*)&smh[A_K0 + sd * VSTR + sj0] = kq;
        *(uint4*)&smh[A_V0 + sd * VSTR + sj0] = vq;
    }
    kq = *(const uint4*)(kb + (size_t)sd * HW_ + NT + sj0);
    vq = *(const uint4*)(vb + (size_t)sd * HW_ + NT + sj0);
    __syncthreads();

    // ---- resident Q A-frags: aq[kchunk][4] ----------------------------
    unsigned aq[2][4];
    {
        int qrow = 16 * w + lr + 8 * (sel & 1);
        #pragma unroll
        for (int c = 0; c < 2; c++)
            ldsm4(aq[c], sbase + (A_QH + qrow * QSTR + 16 * c + 8 * (sel >> 1)) * 2);
    }

    float O[4][4] = {};                 // 16 rows x 32 d, fp32, lives all tiles
    ull l2g = 0, t2g = 0, l2h = 0, t2h = 0;

    // S b-frag (trans): k-row = 16*cc + 8*(sel&1) + lr, n off = 16*ntp + 8*(sel>>1)
    const int tkrow = 8 * (sel & 1) + lr;
    const int tncol = 8 * (sel >> 1);
    // PV b-frag (non-trans, V rows = d = n): row = lr + 8*(sel>>1), col k = j
    const int vrow  = lr + 8 * (sel >> 1);
    const int vcolp = 8 * (sel & 1);

    for (int tile = 0; tile < NTILES; tile++) {
        const unsigned cbuf = (tile & 1) ? A_BSTR : 0u;   // read buffer offset
        const unsigned nbuf = (tile & 1) ? 0u : A_BSTR;   // write buffer offset

        // ---- commit prefetched tile t+1 into the other buffer ---------
        if (tile + 1 < NTILES) {
            *(uint4*)&smh[A_K0 + nbuf + sd * VSTR + sj0] = kq;
            *(uint4*)&smh[A_V0 + nbuf + sd * VSTR + sj0] = vq;
        }
        // ---- prefetch tile t+2 (LDGs overlap the MMAs below) ----------
        if (tile + 2 < NTILES) {
            const int jn = (tile + 2) * NT + sj0;
            kq = *(const uint4*)(kb + (size_t)sd * HW_ + jn);
            vq = *(const uint4*)(vb + (size_t)sd * HW_ + jn);
        }

        // ---- S(=y, log2 domain) = (q*SCL)*k via ldmatrix.trans --------
        float sC[8][4] = {};
        #pragma unroll
        for (int cc = 0; cc < 2; cc++) {
            #pragma unroll
            for (int ntp = 0; ntp < 4; ntp++) {
                unsigned bv[4];
                unsigned off = A_K0 + cbuf + (16 * cc + tkrow) * VSTR + 16 * ntp + tncol;
                ldsm4t(bv, sbase + off * 2);
                mma16816(sC[2 * ntp],     aq[cc][0], aq[cc][1], aq[cc][2], aq[cc][3], bv[0], bv[1]);
                mma16816(sC[2 * ntp + 1], aq[cc][0], aq[cc][1], aq[cc][2], aq[cc][3], bv[2], bv[3]);
            }
        }

        // ---- softmax: p = ex2(y) via MUFU (y = sC directly) -----------
        unsigned PH[8][2];
        #pragma unroll
        for (int nt = 0; nt < 8; nt++) {
            // rows g
            float y0 = sC[nt][0];
            float y1 = sC[nt][1];
            unsigned ph = ex2h2(f2h2(y0, y1));
            PH[nt][0] = ph;
            float p0, p1; h2tof(ph, p0, p1);
            ull p2 = pk2(p0, p1);
            t2g = fma2(p2, pk2(y0, y1), t2g);
            l2g = add2(l2g, p2);
            // rows g+8
            y0 = sC[nt][2];
            y1 = sC[nt][3];
            ph = ex2h2(f2h2(y0, y1));
            PH[nt][1] = ph;
            h2tof(ph, p0, p1);
            p2 = pk2(p0, p1);
            t2h = fma2(p2, pk2(y0, y1), t2h);
            l2h = add2(l2h, p2);
        }

        // ---- O += ph*vh (V non-trans, rows = d) -----------------------
        #pragma unroll
        for (int kc = 0; kc < 4; kc++) {
            unsigned a0 = PH[2 * kc][0],     a1 = PH[2 * kc][1];
            unsigned a2 = PH[2 * kc + 1][0], a3 = PH[2 * kc + 1][1];
            #pragma unroll
            for (int ndp = 0; ndp < 2; ndp++) {
                unsigned bv[4];
                unsigned off = A_V0 + cbuf + (16 * ndp + vrow) * VSTR + 16 * kc + vcolp;
                ldsm4(bv, sbase + off * 2);
                mma16816(O[2 * ndp],     a0, a1, a2, a3, bv[0], bv[1]);
                mma16816(O[2 * ndp + 1], a0, a1, a2, a3, bv[2], bv[3]);
            }
        }

        __syncthreads();   // single barrier: buf[cur] reads + buf[next] writes done
    }

    // ---- finalize: row sums over quad lanes, normalize, write fp16 ----
    const float LN2 = 0.6931471805599453f;
    float lg, tg, lh, th, tmp;
    upk2(l2g, lg, tmp); lg += tmp;
    upk2(t2g, tg, tmp); tg += tmp;
    upk2(l2h, lh, tmp); lh += tmp;
    upk2(t2h, th, tmp); th += tmp;
    #pragma unroll
    for (int off = 1; off <= 2; off <<= 1) {
        lg += __shfl_xor_sync(0xFFFFFFFFu, lg, off);
        tg += __shfl_xor_sync(0xFFFFFFFFu, tg, off);
        lh += __shfl_xor_sync(0xFFFFFFFFu, lh, off);
        th += __shfl_xor_sync(0xFFFFFFFFu, th, off);
    }
    float inv0 = 1.0f / lg;
    float inv1 = 1.0f / lh;

    // g_att_h layout: [b][hw][128], channel = h*32 + d (d even pairs -> u32)
    __half* obase = g_att_h + (size_t)b * HW_ * HID_ + h * DH_;
    const int row0 = m0 + 16 * w + g;
    const int row1 = row0 + 8;
    #pragma unroll
    for (int ntd = 0; ntd < 4; ntd++) {
        int d = 8 * ntd + 2 * qt;
        *(unsigned*)&obase[(size_t)row0 * HID_ + d] = f2h2(O[ntd][0] * inv0, O[ntd][1] * inv0);
        *(unsigned*)&obase[(size_t)row1 * HID_ + d] = f2h2(O[ntd][2] * inv1, O[ntd][3] * inv1);
    }

    float ev = 0.0f;
    if (qt == 0)
        ev = (tg * LN2 * inv0 - logf(lg)) + (th * LN2 * inv1 - logf(lh));
    __syncthreads();
    block_accum(ev, 1, red);
}

__global__ void energy_kernel(float* __restrict__ out, int out_size) {
    if (out_size > NOUT) {
        double e = -0.5 * g_acc[0] + g_acc[1] - 0.5 * g_acc[2];
        out[NOUT] = (float)e;
    }
}

extern "C" void kernel_launch(void* const* d_in, const int* in_sizes, int n_in,
                              void* d_out, int out_size)
{
    const float* x     = (const float*)d_in[0];
    const float* w_qkv = (const float*)d_in[1];
    const float* b_qkv = (const float*)d_in[2];
    const float* w_out = (const float*)d_in[3];
    const float* b_out = (const float*)d_in[4];
    float* out = (float*)d_out;

    void *pqkv = nullptr, *patt = nullptr;
    cudaGetSymbolAddress(&pqkv, g_qkv_h);
    cudaGetSymbolAddress(&patt, g_att_h);

    prep_kernel<<<(WOFF_OUT + C_*HID_) / 256, 256>>>(w_qkv, w_out);
    tc_gemm_qkv_kernel<<<dim3(HW_ / 128, QKV_ / 128, B_), 256>>>(
        x, b_qkv, (__half*)pqkv);
    attn_kernel<<<dim3(HW_ / MT, B_ * HEADS_), 256>>>();
    tc_gemm_out_kernel<<<dim3(HW_ / 128, C_ / 128, B_), 256>>>(
        (const __half*)patt, b_out, out);
    energy_kernel<<<1, 1>>>(out, out_size);
}